// round 4
// baseline (speedup 1.0000x reference)
#include <cuda_runtime.h>
#include <math.h>

#define B_DIM 2
#define S_DIM 2048
#define E_DIM 1024
#define C_DIM 16
#define BS_DIM (B_DIM * S_DIM)          /* 4096  */
#define T3_DIM (BS_DIM * 3)             /* 12288 */

static const size_t BSE = (size_t)BS_DIM * E_DIM;     /* 4194304 */
static const size_t SE  = (size_t)S_DIM * E_DIM;      /* 2097152 */
static const size_t SS  = (size_t)S_DIM * S_DIM;      /* 4194304 */

/* 39 * BSE floats = ~654 MB scratch arena (device globals are the sanctioned
   scratch mechanism; no runtime allocation anywhere). */
__device__ float g_arena[39ULL * 4194304ULL];

/* ------------------------------------------------------------------ */
/* warp / block reductions                                            */
/* ------------------------------------------------------------------ */
__device__ __forceinline__ float warpReduceSum(float v) {
#pragma unroll
    for (int o = 16; o; o >>= 1) v += __shfl_xor_sync(0xffffffffu, v, o);
    return v;
}
__device__ __forceinline__ float warpReduceMax(float v) {
#pragma unroll
    for (int o = 16; o; o >>= 1) v = fmaxf(v, __shfl_xor_sync(0xffffffffu, v, o));
    return v;
}
__device__ float blockReduceSum(float v) {
    __shared__ float sh[32];
    __syncthreads();
    int lane = threadIdx.x & 31, wid = threadIdx.x >> 5;
    v = warpReduceSum(v);
    if (lane == 0) sh[wid] = v;
    __syncthreads();
    float r = (threadIdx.x < (blockDim.x >> 5)) ? sh[threadIdx.x] : 0.f;
    r = warpReduceSum(r);
    if (threadIdx.x == 0) sh[0] = r;
    __syncthreads();
    return sh[0];
}
__device__ float blockReduceMax(float v) {
    __shared__ float sh[32];
    __syncthreads();
    int lane = threadIdx.x & 31, wid = threadIdx.x >> 5;
    v = warpReduceMax(v);
    if (lane == 0) sh[wid] = v;
    __syncthreads();
    float r = (threadIdx.x < (blockDim.x >> 5)) ? sh[threadIdx.x] : -3.4e38f;
    r = warpReduceMax(r);
    if (threadIdx.x == 0) sh[0] = r;
    __syncthreads();
    return sh[0];
}

/* ------------------------------------------------------------------ */
/* GEMM: C = alpha * A @ op(B) + beta * C (+ bias[col])               */
/* A: (M,K) row-major. TRANSB: B is (N,K), else (K,N).                */
/* blockIdx.z batches via strides. M,N mult of 128; K mult of 8.      */
/* ------------------------------------------------------------------ */
template <bool TRANSB>
__global__ void __launch_bounds__(256) gemm_kernel(
    const float* __restrict__ A, const float* __restrict__ Bm,
    const float* __restrict__ bias, float* __restrict__ C,
    int M, int N, int K, size_t sA, size_t sB, size_t sC,
    float alpha, float beta)
{
    __shared__ float As[8][128];
    __shared__ float Bs[8][128];
    const float* Ab = A + (size_t)blockIdx.z * sA;
    const float* Bb = Bm + (size_t)blockIdx.z * sB;
    float* Cb = C + (size_t)blockIdx.z * sC;
    const int bm = blockIdx.y * 128;
    const int bn = blockIdx.x * 128;
    const int tid = threadIdx.x;
    const int tx = tid & 15;
    const int ty = tid >> 4;

    float acc[8][8];
#pragma unroll
    for (int i = 0; i < 8; i++)
#pragma unroll
        for (int j = 0; j < 8; j++) acc[i][j] = 0.f;

    const int lrow = tid >> 1;        /* 0..127 */
    const int lcol = (tid & 1) * 4;   /* 0 or 4 */
    const int nkr = tid >> 5;         /* 0..7   */
    const int nnc = (tid & 31) * 4;   /* 0..124 */

    for (int k0 = 0; k0 < K; k0 += 8) {
        float4 av = *reinterpret_cast<const float4*>(
            &Ab[(size_t)(bm + lrow) * K + k0 + lcol]);
        As[lcol + 0][lrow] = av.x;
        As[lcol + 1][lrow] = av.y;
        As[lcol + 2][lrow] = av.z;
        As[lcol + 3][lrow] = av.w;
        if (TRANSB) {
            float4 bv = *reinterpret_cast<const float4*>(
                &Bb[(size_t)(bn + lrow) * K + k0 + lcol]);
            Bs[lcol + 0][lrow] = bv.x;
            Bs[lcol + 1][lrow] = bv.y;
            Bs[lcol + 2][lrow] = bv.z;
            Bs[lcol + 3][lrow] = bv.w;
        } else {
            float4 bv = *reinterpret_cast<const float4*>(
                &Bb[(size_t)(k0 + nkr) * N + bn + nnc]);
            Bs[nkr][nnc + 0] = bv.x;
            Bs[nkr][nnc + 1] = bv.y;
            Bs[nkr][nnc + 2] = bv.z;
            Bs[nkr][nnc + 3] = bv.w;
        }
        __syncthreads();
#pragma unroll
        for (int kk = 0; kk < 8; kk++) {
            float4 a0 = *reinterpret_cast<const float4*>(&As[kk][ty * 4]);
            float4 a1 = *reinterpret_cast<const float4*>(&As[kk][64 + ty * 4]);
            float4 b0 = *reinterpret_cast<const float4*>(&Bs[kk][tx * 4]);
            float4 b1 = *reinterpret_cast<const float4*>(&Bs[kk][64 + tx * 4]);
            float ar[8] = {a0.x, a0.y, a0.z, a0.w, a1.x, a1.y, a1.z, a1.w};
            float br[8] = {b0.x, b0.y, b0.z, b0.w, b1.x, b1.y, b1.z, b1.w};
#pragma unroll
            for (int i = 0; i < 8; i++)
#pragma unroll
                for (int j = 0; j < 8; j++) acc[i][j] += ar[i] * br[j];
        }
        __syncthreads();
    }

#pragma unroll
    for (int i = 0; i < 8; i++) {
        int row = bm + ((i < 4) ? (ty * 4 + i) : (64 + ty * 4 + i - 4));
#pragma unroll
        for (int h = 0; h < 2; h++) {
            int col = bn + (h ? (64 + tx * 4) : (tx * 4));
            float4 o;
            o.x = alpha * acc[i][h * 4 + 0];
            o.y = alpha * acc[i][h * 4 + 1];
            o.z = alpha * acc[i][h * 4 + 2];
            o.w = alpha * acc[i][h * 4 + 3];
            if (bias) {
                float4 bv = *reinterpret_cast<const float4*>(&bias[col]);
                o.x += bv.x; o.y += bv.y; o.z += bv.z; o.w += bv.w;
            }
            float4* cp = reinterpret_cast<float4*>(&Cb[(size_t)row * N + col]);
            if (beta != 0.f) {
                float4 old = *cp;
                o.x += beta * old.x; o.y += beta * old.y;
                o.z += beta * old.z; o.w += beta * old.w;
            }
            *cp = o;
        }
    }
}

static void gemm(const float* A, const float* Bm, const float* bias, float* C,
                 int M, int N, int K, int batch, size_t sA, size_t sB, size_t sC,
                 float alpha, float beta, bool transB)
{
    dim3 grid(N / 128, M / 128, batch), block(256);
    if (transB)
        gemm_kernel<true><<<grid, block>>>(A, Bm, bias, C, M, N, K, sA, sB, sC, alpha, beta);
    else
        gemm_kernel<false><<<grid, block>>>(A, Bm, bias, C, M, N, K, sA, sB, sC, alpha, beta);
}

/* ------------------------------------------------------------------ */
/* DFT / DCT basis fills                                              */
/* ------------------------------------------------------------------ */
__global__ void fill_dft_kernel(float* __restrict__ Cm, float* __restrict__ Sm)
{
    size_t i = (size_t)blockIdx.x * blockDim.x + threadIdx.x;
    if (i >= (size_t)S_DIM * S_DIM) return;
    int s = (int)(i / S_DIM), t = (int)(i % S_DIM);
    long long p = ((long long)s * (long long)t) & (S_DIM - 1); /* exact mod */
    double ang = (double)p * (6.283185307179586476925286766559 / (double)S_DIM);
    Cm[i] = (float)cos(ang);
    Sm[i] = (float)sin(ang);
}

/* Replicate jax's float32 argument arithmetic exactly, then accurate cos. */
__global__ void fill_dct_kernel(float* __restrict__ D, float* __restrict__ I)
{
    size_t idx = (size_t)blockIdx.x * blockDim.x + threadIdx.x;
    if (idx >= (size_t)S_DIM * S_DIM) return;
    int i = (int)(idx / S_DIM), j = (int)(idx % S_DIM);
    const float PI_F = (float)M_PI;
    float s0 = (float)sqrt(1.0 / (double)S_DIM);
    float s1 = (float)sqrt(2.0 / (double)S_DIM);
    /* D[i,j] = cos( fl(fl(pi*i) * (2j+1)) / 4096 ) * (i==0 ? s0 : s1) */
    float a = PI_F * (float)i;
    float b = a * (float)(2 * j + 1);
    float argd = b / (float)(2 * S_DIM);
    D[idx] = (float)cos((double)argd) * (i == 0 ? s0 : s1);
    /* I[i,j] = cos( fl(fl(pi*j) * (2i+1)) / 4096 ) * (j==0 ? s0 : s1) */
    float a2 = PI_F * (float)j;
    float b2 = a2 * (float)(2 * i + 1);
    float argi = b2 / (float)(2 * S_DIM);
    I[idx] = (float)cos((double)argi) * (j == 0 ? s0 : s1);
}

/* ------------------------------------------------------------------ */
/* conv1d (kernel=3, pad 1): out[b,s,c] = sum_{e,k} W[c,e,k] x[b,s+k-1,e] */
/* ------------------------------------------------------------------ */
__global__ void __launch_bounds__(512) conv1d_kernel(
    const float* __restrict__ x, const float* __restrict__ Wc,
    const float* __restrict__ bc, float* __restrict__ out)
{
    __shared__ float xs[3 * E_DIM];
    int bs = blockIdx.x;
    int b = bs >> 11;
    int s = bs & 2047;
    for (int i = threadIdx.x; i < 3 * E_DIM; i += 512) {
        int tap = i >> 10;
        int e = i & 1023;
        int sp = s + tap - 1;
        xs[i] = (sp >= 0 && sp < S_DIM)
                    ? x[((size_t)b * S_DIM + sp) * E_DIM + e]
                    : 0.f;
    }
    __syncthreads();
    int c = threadIdx.x >> 5, lane = threadIdx.x & 31;
    const float* w = Wc + (size_t)c * E_DIM * 3;
    float acc = 0.f;
    for (int e = lane; e < E_DIM; e += 32) {
        float x0 = xs[e], x1 = xs[E_DIM + e], x2 = xs[2 * E_DIM + e];
        acc += w[e * 3 + 0] * x0 + w[e * 3 + 1] * x1 + w[e * 3 + 2] * x2;
    }
    acc = warpReduceSum(acc);
    if (lane == 0) out[(size_t)bs * C_DIM + c] = acc + bc[c];
}

/* fw = softmax over C of F (C,E) */
__global__ void fweights_kernel(const float* __restrict__ F, float* __restrict__ fw)
{
    int e = blockIdx.x * blockDim.x + threadIdx.x;
    if (e >= E_DIM) return;
    float v[C_DIM], m = -3.4e38f;
#pragma unroll
    for (int c = 0; c < C_DIM; c++) { v[c] = F[c * E_DIM + e]; m = fmaxf(m, v[c]); }
    float s = 0.f;
#pragma unroll
    for (int c = 0; c < C_DIM; c++) { v[c] = expf(v[c] - m); s += v[c]; }
    float inv = 1.f / s;
#pragma unroll
    for (int c = 0; c < C_DIM; c++) fw[c * E_DIM + e] = v[c] * inv;
}

/* out[bs,e] = sum_c ch[bs,c] * fw[c,e] */
__global__ void mix_kernel(const float* __restrict__ ch, const float* __restrict__ fw,
                           float* __restrict__ out)
{
    size_t i = (size_t)blockIdx.x * blockDim.x + threadIdx.x;
    if (i >= (size_t)BS_DIM * E_DIM) return;
    int e = (int)(i & 1023);
    size_t bs = i >> 10;
    const float* cr = ch + bs * C_DIM;
    float a = 0.f;
#pragma unroll
    for (int c = 0; c < C_DIM; c++) a += cr[c] * fw[c * E_DIM + e];
    out[i] = a;
}

/* ------------------------------------------------------------------ */
/* softmax over rows of scores (real / complex-angle variants)        */
/* ------------------------------------------------------------------ */
__global__ void softmax_rows_real(float* __restrict__ Sc, int cols, float scale)
{
    float* row = Sc + (size_t)blockIdx.x * cols;
    int tid = threadIdx.x;
    float m = -3.4e38f;
    for (int i = tid; i < cols; i += blockDim.x) m = fmaxf(m, row[i]);
    m = blockReduceMax(m);
    float s = 0.f;
    for (int i = tid; i < cols; i += blockDim.x) {
        float p = expf((row[i] - m) * scale);
        row[i] = p;
        s += p;
    }
    s = blockReduceSum(s);
    float inv = 1.f / s;
    for (int i = tid; i < cols; i += blockDim.x) row[i] *= inv;
}

/* Replaces (Sr,Si) in place with cw = softmax(Sr*scale) * exp(i*angle(S)). */
__global__ void softmax_rows_complex(float* __restrict__ Sr, float* __restrict__ Si,
                                     int cols, float scale)
{
    size_t off = (size_t)blockIdx.x * cols;
    float* rr = Sr + off;
    float* ri = Si + off;
    int tid = threadIdx.x;
    float m = -3.4e38f;
    for (int i = tid; i < cols; i += blockDim.x) m = fmaxf(m, rr[i]);
    m = blockReduceMax(m);
    float s = 0.f;
    for (int i = tid; i < cols; i += blockDim.x) {
        float ar = rr[i], ai = ri[i];
        float p = expf((ar - m) * scale);
        s += p;
        float mag = sqrtf(ar * ar + ai * ai);
        float ur, ui;
        if (mag > 0.f) { ur = ar / mag; ui = ai / mag; }
        else           { ur = 1.f;      ui = 0.f;      } /* angle(0)=0 */
        rr[i] = p * ur;
        ri[i] = p * ui;
    }
    s = blockReduceSum(s);
    float inv = 1.f / s;
    for (int i = tid; i < cols; i += blockDim.x) { rr[i] *= inv; ri[i] *= inv; }
}

/* ------------------------------------------------------------------ */
/* Haar wavelet: one level; details -> sbuf at offset L/2, approx -> nxt */
/* ------------------------------------------------------------------ */
__global__ void haar_level_kernel(const float* __restrict__ cur, float* __restrict__ nxt,
                                  float* __restrict__ sbuf, int L)
{
    int half = L >> 1;
    size_t total = (size_t)B_DIM * half * E_DIM;
    size_t i = (size_t)blockIdx.x * blockDim.x + threadIdx.x;
    if (i >= total) return;
    int e = (int)(i % E_DIM);
    size_t t = i / E_DIM;
    int j = (int)(t % half);
    int b = (int)(t / half);
    const float SQ2F = 1.41421356237309515f;
    float ev = cur[((size_t)b * L + 2 * j) * E_DIM + e];
    float ov = cur[((size_t)b * L + 2 * j + 1) * E_DIM + e];
    sbuf[((size_t)b * S_DIM + half + j) * E_DIM + e] = (ev - ov) / SQ2F;
    float ap = (ev + ov) / SQ2F;
    nxt[((size_t)b * half + j) * E_DIM + e] = ap;
    if (half == 1) sbuf[((size_t)b * S_DIM) * E_DIM + e] = ap;
}

/* x[(bs*3+d)*E + e] = out_d[bs*E + e] */
__global__ void stack3_kernel(const float* __restrict__ f, const float* __restrict__ w,
                              const float* __restrict__ c, float* __restrict__ x)
{
    size_t i = (size_t)blockIdx.x * blockDim.x + threadIdx.x;
    if (i >= 3 * (size_t)BS_DIM * E_DIM) return;
    size_t e = i % E_DIM;
    size_t t = i / E_DIM;
    size_t d = t % 3, bs = t / 3;
    const float* src = (d == 0) ? f : ((d == 1) ? w : c);
    x[i] = src[bs * E_DIM + e];
}

/* ------------------------------------------------------------------ */
/* MHA over L=3 tokens, 16 heads, hd=64. One warp per (group, head).  */
/* ------------------------------------------------------------------ */
__global__ void mha_small_attn(const float* __restrict__ qkv, float* __restrict__ out)
{
    int gw = (int)(((size_t)blockIdx.x * blockDim.x + threadIdx.x) >> 5);
    int lane = threadIdx.x & 31;
    if (gw >= BS_DIM * 16) return;
    int g = gw >> 4, h = gw & 15;
    const float* base = qkv + (size_t)g * 3 * 3072 + h * 64;
    float q[3][2], k[3][2], v[3][2];
#pragma unroll
    for (int l = 0; l < 3; l++) {
        q[l][0] = base[(size_t)l * 3072 + lane];
        q[l][1] = base[(size_t)l * 3072 + lane + 32];
        k[l][0] = base[(size_t)l * 3072 + 1024 + lane];
        k[l][1] = base[(size_t)l * 3072 + 1024 + lane + 32];
        v[l][0] = base[(size_t)l * 3072 + 2048 + lane];
        v[l][1] = base[(size_t)l * 3072 + 2048 + lane + 32];
    }
    float sc[3][3];
#pragma unroll
    for (int l = 0; l < 3; l++)
#pragma unroll
        for (int m = 0; m < 3; m++) {
            float t = q[l][0] * k[m][0] + q[l][1] * k[m][1];
#pragma unroll
            for (int o = 16; o; o >>= 1) t += __shfl_xor_sync(0xffffffffu, t, o);
            sc[l][m] = t * 0.125f; /* 1/sqrt(64) */
        }
    float a[3][3];
#pragma unroll
    for (int l = 0; l < 3; l++) {
        float m0 = fmaxf(sc[l][0], fmaxf(sc[l][1], sc[l][2]));
        float e0 = expf(sc[l][0] - m0);
        float e1 = expf(sc[l][1] - m0);
        float e2 = expf(sc[l][2] - m0);
        float s = e0 + e1 + e2;
        a[l][0] = e0 / s; a[l][1] = e1 / s; a[l][2] = e2 / s;
    }
    float* ob = out + (size_t)g * 3 * 1024 + h * 64;
#pragma unroll
    for (int l = 0; l < 3; l++) {
        float o0 = a[l][0] * v[0][0] + a[l][1] * v[1][0] + a[l][2] * v[2][0];
        float o1 = a[l][0] * v[0][1] + a[l][1] * v[1][1] + a[l][2] * v[2][1];
        ob[(size_t)l * 1024 + lane] = o0;
        ob[(size_t)l * 1024 + lane + 32] = o1;
    }
}

/* ------------------------------------------------------------------ */
/* Orchestration                                                      */
/* ------------------------------------------------------------------ */
extern "C" void kernel_launch(void* const* d_in, const int* in_sizes, int n_in,
                              void* d_out, int out_size)
{
    (void)in_sizes; (void)n_in; (void)out_size;
    const float* query  = (const float*)d_in[0];
    const float* Wp_f   = (const float*)d_in[1];
    const float* bp_f   = (const float*)d_in[2];
    const float* Wc_f   = (const float*)d_in[3];
    const float* bc_f   = (const float*)d_in[4];
    const float* Ff     = (const float*)d_in[5];
    const float* Wp_w   = (const float*)d_in[6];
    const float* bp_w   = (const float*)d_in[7];
    const float* Wc_w   = (const float*)d_in[8];
    const float* bc_w   = (const float*)d_in[9];
    const float* Fw     = (const float*)d_in[10];
    const float* Wp_c   = (const float*)d_in[11];
    const float* bp_c   = (const float*)d_in[12];
    const float* Wc_c   = (const float*)d_in[13];
    const float* bc_c   = (const float*)d_in[14];
    const float* Fc     = (const float*)d_in[15];
    const float* mha_iw = (const float*)d_in[16];
    const float* mha_ib = (const float*)d_in[17];
    const float* mha_ow = (const float*)d_in[18];
    const float* mha_ob = (const float*)d_in[19];
    const float* fus_W  = (const float*)d_in[20];
    const float* fus_b  = (const float*)d_in[21];
    float* out = (float*)d_out;

    float* arena = nullptr;
    cudaGetSymbolAddress((void**)&arena, g_arena);

    float* xd    = arena + 0 * BSE;
    float* sr    = arena + 1 * BSE;   /* spectral real / haar / dct coeffs */
    float* si    = arena + 2 * BSE;   /* spectral imag */
    float* chr   = arena + 3 * BSE;   /* mixed channels real (q=k=v) */
    float* chi   = arena + 4 * BSE;
    float* or_   = arena + 5 * BSE;   /* attention out real */
    float* oi    = arena + 6 * BSE;
    float* outf  = arena + 7 * BSE;
    float* outw  = arena + 8 * BSE;
    float* outc  = arena + 9 * BSE;
    float* scr   = arena + 10 * BSE;  /* scores real (2*BSE) */
    float* sci   = arena + 12 * BSE;  /* scores imag (2*BSE) */
    float* cosM  = arena + 14 * BSE;
    float* sinM  = arena + 15 * BSE;
    float* dctD  = arena + 16 * BSE;
    float* dctI  = arena + 17 * BSE;
    float* xstk  = arena + 18 * BSE;  /* (12288,1024) : 3*BSE */
    float* qkv   = arena + 21 * BSE;  /* (12288,3072) : 9*BSE */
    float* att   = arena + 30 * BSE;  /* (12288,1024) : 3*BSE */
    float* corr  = arena + 33 * BSE;  /* (12288,1024) : 3*BSE */
    float* chtr  = arena + 36 * BSE;                  /* (BS,16)  */
    float* chti  = arena + 36 * BSE + 65536;          /* (BS,16)  */
    float* fwbuf = arena + 36 * BSE + 2 * 65536;      /* (16,E)   */
    float* haar0 = arena + 37 * BSE;
    float* haar1 = arena + 38 * BSE;

    const float inv_sqE = 1.f / 32.f;  /* 1/sqrt(E) */
    const int NB_MIX = (int)((BSE + 255) / 256);

    /* basis matrices */
    fill_dft_kernel<<<(unsigned)((SS + 255) / 256), 256>>>(cosM, sinM);
    fill_dct_kernel<<<(unsigned)((SS + 255) / 256), 256>>>(dctD, dctI);

    /* ============ Fourier domain ============ */
    gemm(query, Wp_f, bp_f, xd, BS_DIM, E_DIM, E_DIM, 1, 0, 0, 0, 1.f, 0.f, true);
    /* Xr = Cos @ xd ; Xi = -Sin @ xd (batched over B) */
    gemm(cosM, xd, nullptr, sr, S_DIM, E_DIM, S_DIM, B_DIM, 0, SE, SE, 1.f, 0.f, false);
    gemm(sinM, xd, nullptr, si, S_DIM, E_DIM, S_DIM, B_DIM, 0, SE, SE, -1.f, 0.f, false);
    conv1d_kernel<<<BS_DIM, 512>>>(sr, Wc_f, bc_f, chtr);
    conv1d_kernel<<<BS_DIM, 512>>>(si, Wc_f, bc_f, chti);
    fweights_kernel<<<4, 256>>>(Ff, fwbuf);
    mix_kernel<<<NB_MIX, 256>>>(chtr, fwbuf, chr);
    mix_kernel<<<NB_MIX, 256>>>(chti, fwbuf, chi);
    /* complex scores: Sr = QrKr^T - QiKi^T ; Si = QrKi^T + QiKr^T */
    gemm(chr, chr, nullptr, scr, S_DIM, S_DIM, E_DIM, B_DIM, SE, SE, SS, 1.f, 0.f, true);
    gemm(chi, chi, nullptr, scr, S_DIM, S_DIM, E_DIM, B_DIM, SE, SE, SS, -1.f, 1.f, true);
    gemm(chr, chi, nullptr, sci, S_DIM, S_DIM, E_DIM, B_DIM, SE, SE, SS, 1.f, 0.f, true);
    gemm(chi, chr, nullptr, sci, S_DIM, S_DIM, E_DIM, B_DIM, SE, SE, SS, 1.f, 1.f, true);
    softmax_rows_complex<<<BS_DIM, 256>>>(scr, sci, S_DIM, inv_sqE);
    /* out = cw @ v (complex) */
    gemm(scr, chr, nullptr, or_, S_DIM, E_DIM, S_DIM, B_DIM, SS, SE, SE, 1.f, 0.f, false);
    gemm(sci, chi, nullptr, or_, S_DIM, E_DIM, S_DIM, B_DIM, SS, SE, SE, -1.f, 1.f, false);
    gemm(scr, chi, nullptr, oi, S_DIM, E_DIM, S_DIM, B_DIM, SS, SE, SE, 1.f, 0.f, false);
    gemm(sci, chr, nullptr, oi, S_DIM, E_DIM, S_DIM, B_DIM, SS, SE, SE, 1.f, 1.f, false);
    /* outf = real(ifft) = (Cos@Or - Sin@Oi)/S */
    gemm(cosM, or_, nullptr, outf, S_DIM, E_DIM, S_DIM, B_DIM, 0, SE, SE,
         1.f / (float)S_DIM, 0.f, false);
    gemm(sinM, oi, nullptr, outf, S_DIM, E_DIM, S_DIM, B_DIM, 0, SE, SE,
         -1.f / (float)S_DIM, 1.f, false);

    /* ============ Wavelet domain ============ */
    gemm(query, Wp_w, bp_w, xd, BS_DIM, E_DIM, E_DIM, 1, 0, 0, 0, 1.f, 0.f, true);
    {
        const float* cur = xd;
        float* nx = haar0;
        for (int L = S_DIM; L >= 2; L >>= 1) {
            size_t tot = (size_t)B_DIM * (L >> 1) * E_DIM;
            haar_level_kernel<<<(unsigned)((tot + 255) / 256), 256>>>(cur, nx, sr, L);
            cur = nx;
            nx = (nx == haar0) ? haar1 : haar0;
        }
    }
    conv1d_kernel<<<BS_DIM, 512>>>(sr, Wc_w, bc_w, chtr);
    fweights_kernel<<<4, 256>>>(Fw, fwbuf);
    mix_kernel<<<NB_MIX, 256>>>(chtr, fwbuf, chr);
    gemm(chr, chr, nullptr, scr, S_DIM, S_DIM, E_DIM, B_DIM, SE, SE, SS, 1.f, 0.f, true);
    softmax_rows_real<<<BS_DIM, 256>>>(scr, S_DIM, inv_sqE);
    gemm(scr, chr, nullptr, outw, S_DIM, E_DIM, S_DIM, B_DIM, SS, SE, SE, 1.f, 0.f, false);

    /* ============ Cosine (DCT) domain ============ */
    gemm(query, Wp_c, bp_c, xd, BS_DIM, E_DIM, E_DIM, 1, 0, 0, 0, 1.f, 0.f, true);
    gemm(dctD, xd, nullptr, sr, S_DIM, E_DIM, S_DIM, B_DIM, 0, SE, SE, 1.f, 0.f, false);
    conv1d_kernel<<<BS_DIM, 512>>>(sr, Wc_c, bc_c, chtr);
    fweights_kernel<<<4, 256>>>(Fc, fwbuf);
    mix_kernel<<<NB_MIX, 256>>>(chtr, fwbuf, chr);
    gemm(chr, chr, nullptr, scr, S_DIM, S_DIM, E_DIM, B_DIM, SE, SE, SS, 1.f, 0.f, true);
    softmax_rows_real<<<BS_DIM, 256>>>(scr, S_DIM, inv_sqE);
    gemm(scr, chr, nullptr, or_, S_DIM, E_DIM, S_DIM, B_DIM, SS, SE, SE, 1.f, 0.f, false);
    gemm(dctI, or_, nullptr, outc, S_DIM, E_DIM, S_DIM, B_DIM, 0, SE, SE, 1.f, 0.f, false);

    /* ============ cross-domain MHA + fusion ============ */
    stack3_kernel<<<(unsigned)((3 * BSE + 255) / 256), 256>>>(outf, outw, outc, xstk);
    gemm(xstk, mha_iw, mha_ib, qkv, T3_DIM, 3 * E_DIM, E_DIM, 1, 0, 0, 0, 1.f, 0.f, true);
    mha_small_attn<<<(BS_DIM * 16 * 32) / 256, 256>>>(qkv, att);
    gemm(att, mha_ow, mha_ob, corr, T3_DIM, E_DIM, E_DIM, 1, 0, 0, 0, 1.f, 0.f, true);
    /* corr (12288,1024) viewed as (4096,3072); final: @ fus_W^T + fus_b */
    gemm(corr, fus_W, fus_b, out, BS_DIM, E_DIM, 3 * E_DIM, 1, 0, 0, 0, 1.f, 0.f, true);
}

// round 10
// speedup vs baseline: 1.6315x; 1.6315x over previous
#include <cuda_runtime.h>
#include <cuda_bf16.h>
#include <math.h>
#include <stdint.h>

#define B_DIM 2
#define S_DIM 2048
#define E_DIM 1024
#define C_DIM 16
#define BS_DIM (B_DIM * S_DIM)          /* 4096  */
#define T3_DIM (BS_DIM * 3)             /* 12288 */

typedef __nv_bfloat16 bf;

static const size_t BSE = (size_t)BS_DIM * E_DIM;     /* 4194304 */
static const size_t SE  = (size_t)S_DIM * E_DIM;      /* 2097152 */
static const size_t SS  = (size_t)S_DIM * S_DIM;      /* 4194304 */
#define BF_UNIT 4194304ULL

/* fp32 scratch: 32 units of BSE floats (~537 MB) */
__device__ float g_arena[32ULL * BF_UNIT];
/* bf16 scratch: 56 units (~470 MB) */
__device__ bf g_bfarena[56ULL * BF_UNIT];

__device__ __forceinline__ uint32_t smem_to_u32(const void* p) {
    uint32_t a;
    asm("{ .reg .u64 t; cvta.to.shared.u64 t, %1; cvt.u32.u64 %0, t; }"
        : "=r"(a) : "l"(p));
    return a;
}

/* ================= warp-MMA primitives (non-'a', compute_103-safe) ===== */
__device__ __forceinline__ void ldmx4(uint32_t* r, uint32_t a) {
    asm volatile("ldmatrix.sync.aligned.m8n8.x4.shared.b16 {%0,%1,%2,%3}, [%4];"
                 : "=r"(r[0]), "=r"(r[1]), "=r"(r[2]), "=r"(r[3]) : "r"(a));
}
__device__ __forceinline__ void ldmx2(uint32_t* r, uint32_t a) {
    asm volatile("ldmatrix.sync.aligned.m8n8.x2.shared.b16 {%0,%1}, [%2];"
                 : "=r"(r[0]), "=r"(r[1]) : "r"(a));
}
__device__ __forceinline__ void mma16816(float* c, const uint32_t* a, const uint32_t* b) {
    asm volatile(
        "mma.sync.aligned.m16n8k16.row.col.f32.bf16.bf16.f32 "
        "{%0,%1,%2,%3}, {%4,%5,%6,%7}, {%8,%9}, {%0,%1,%2,%3};"
        : "+f"(c[0]), "+f"(c[1]), "+f"(c[2]), "+f"(c[3])
        : "r"(a[0]), "r"(a[1]), "r"(a[2]), "r"(a[3]), "r"(b[0]), "r"(b[1]));
}
__device__ __forceinline__ void cpa16(uint32_t d, const void* s) {
    asm volatile("cp.async.cg.shared.global [%0], [%1], 16;" :: "r"(d), "l"(s));
}
#define CP_COMMIT() asm volatile("cp.async.commit_group;" ::: "memory")
#define CP_WAIT0()  asm volatile("cp.async.wait_group 0;" ::: "memory")
#define CP_WAIT1()  asm volatile("cp.async.wait_group 1;" ::: "memory")

/* ================= reductions ========================================== */
__device__ __forceinline__ float warpReduceSum(float v) {
#pragma unroll
    for (int o = 16; o; o >>= 1) v += __shfl_xor_sync(0xffffffffu, v, o);
    return v;
}
__device__ __forceinline__ float warpReduceMax(float v) {
#pragma unroll
    for (int o = 16; o; o >>= 1) v = fmaxf(v, __shfl_xor_sync(0xffffffffu, v, o));
    return v;
}
__device__ float blockReduceSum(float v) {
    __shared__ float sh[32];
    __syncthreads();
    int lane = threadIdx.x & 31, wid = threadIdx.x >> 5;
    v = warpReduceSum(v);
    if (lane == 0) sh[wid] = v;
    __syncthreads();
    float r = (threadIdx.x < (blockDim.x >> 5)) ? sh[threadIdx.x] : 0.f;
    r = warpReduceSum(r);
    if (threadIdx.x == 0) sh[0] = r;
    __syncthreads();
    return sh[0];
}
__device__ float blockReduceMax(float v) {
    __shared__ float sh[32];
    __syncthreads();
    int lane = threadIdx.x & 31, wid = threadIdx.x >> 5;
    v = warpReduceMax(v);
    if (lane == 0) sh[wid] = v;
    __syncthreads();
    float r = (threadIdx.x < (blockDim.x >> 5)) ? sh[threadIdx.x] : -3.4e38f;
    r = warpReduceMax(r);
    if (threadIdx.x == 0) sh[0] = r;
    __syncthreads();
    return sh[0];
}

/* ================= tensor-core split-fp32 GEMM (HMMA path) ============= */
/* C(M,N) = alpha * A(M,K) @ B(N,K)^T + beta*C + bias[col]                 */
/* A,B supplied as bf16 hi/lo pairs. 256 threads, tile 128x128, BK=64.     */
#define PITCH 144                        /* bytes per 64-elem bf16 row      */
#define TILE_B (128 * PITCH)             /* 18432 bytes                     */
#define STAGE_B (4 * TILE_B)             /* Ah,Al,Bh,Bl                     */
#define GEMM_SMEM (2 * STAGE_B)          /* 147456 bytes (2 stages)         */

__global__ void __launch_bounds__(256) gemm_tc(
    const bf* __restrict__ Ah, const bf* __restrict__ Al,
    const bf* __restrict__ Bh, const bf* __restrict__ Bl,
    const float* __restrict__ bias, float* __restrict__ C,
    int M, int N, int K, size_t sA, size_t sB, size_t sC,
    float alpha, float beta)
{
    extern __shared__ char smem[];
    const uint32_t su = smem_to_u32(smem);
    const int tid = threadIdx.x;
    const int lane = tid & 31, wid = tid >> 5;
    const int wm = (wid >> 2) * 64;      /* warp M offset in tile */
    const int wn = (wid & 3) * 32;       /* warp N offset in tile */

    const size_t zb = blockIdx.z;
    float* Cb = C + zb * sC;
    const int bm = blockIdx.y * 128;
    const int bn = blockIdx.x * 128;

    const bf* srcs[4];
    srcs[0] = Ah + zb * sA + (size_t)bm * K;
    srcs[1] = Al + zb * sA + (size_t)bm * K;
    srcs[2] = Bh + zb * sB + (size_t)bn * K;
    srcs[3] = Bl + zb * sB + (size_t)bn * K;

    float c[4][4][4];
#pragma unroll
    for (int i = 0; i < 4; i++)
#pragma unroll
        for (int j = 0; j < 4; j++)
#pragma unroll
            for (int k = 0; k < 4; k++) c[i][j][k] = 0.f;

    const int nch = K / 64;

#define LOADSTAGE(s, k0) do {                                              \
        uint32_t sb_ = su + (s) * STAGE_B;                                 \
        _Pragma("unroll")                                                  \
        for (int t_ = 0; t_ < 4; t_++) {                                   \
            _Pragma("unroll")                                              \
            for (int j_ = 0; j_ < 4; j_++) {                               \
                int idx_ = j_ * 256 + tid;                                 \
                int row_ = idx_ >> 3;                                      \
                int cc_ = idx_ & 7;                                        \
                uint32_t d_ = sb_ + t_ * TILE_B + row_ * PITCH + cc_ * 16; \
                const void* g_ = srcs[t_] + (size_t)row_ * K + (k0) + cc_ * 8; \
                cpa16(d_, g_);                                             \
            }                                                              \
        }                                                                  \
        CP_COMMIT();                                                       \
    } while (0)

    LOADSTAGE(0, 0);

    /* fragment address bases (per lane) */
    const int qa = lane >> 3;            /* 0..3 */
    const int ra = lane & 7;
    const int arow = (qa & 1) * 8 + ra;  /* A row within 16-row tile  */
    const int acol = (qa >> 1) * 16;     /* A 8-col chunk byte offset */
    const int qb = (lane >> 3) & 1;
    const int brow = lane & 7;
    const int bcol = qb * 16;

    for (int i = 0; i < nch; i++) {
        if (i + 1 < nch) { LOADSTAGE((i + 1) & 1, (i + 1) * 64); CP_WAIT1(); }
        else             { CP_WAIT0(); }
        __syncthreads();

        const uint32_t sb = su + (i & 1) * STAGE_B;
#pragma unroll
        for (int kk = 0; kk < 4; kk++) {
            uint32_t fAh[4][4], fAl[4][4], fBh[4][2], fBl[4][2];
#pragma unroll
            for (int mt = 0; mt < 4; mt++) {
                uint32_t a = sb + (wm + mt * 16 + arow) * PITCH + kk * 32 + acol;
                ldmx4(fAh[mt], a);
                ldmx4(fAl[mt], a + TILE_B);
            }
#pragma unroll
            for (int nt = 0; nt < 4; nt++) {
                uint32_t a = sb + 2 * TILE_B + (wn + nt * 8 + brow) * PITCH + kk * 32 + bcol;
                ldmx2(fBh[nt], a);
                ldmx2(fBl[nt], a + TILE_B);
            }
#pragma unroll
            for (int mt = 0; mt < 4; mt++)
#pragma unroll
                for (int nt = 0; nt < 4; nt++) {
                    mma16816(c[mt][nt], fAh[mt], fBh[nt]);
                    mma16816(c[mt][nt], fAh[mt], fBl[nt]);
                    mma16816(c[mt][nt], fAl[mt], fBh[nt]);
                }
        }
        __syncthreads();
    }

    /* epilogue: direct fragment stores */
    const int g = lane >> 2, t4 = lane & 3;
#pragma unroll
    for (int mt = 0; mt < 4; mt++) {
#pragma unroll
        for (int nt = 0; nt < 4; nt++) {
            const int col = bn + wn + nt * 8 + 2 * t4;
            const int row0 = bm + wm + mt * 16 + g;
            float bv0 = 0.f, bv1 = 0.f;
            if (bias) { bv0 = bias[col]; bv1 = bias[col + 1]; }
            float2* p0 = reinterpret_cast<float2*>(&Cb[(size_t)row0 * N + col]);
            float2* p1 = reinterpret_cast<float2*>(&Cb[(size_t)(row0 + 8) * N + col]);
            float2 v0, v1;
            v0.x = alpha * c[mt][nt][0] + bv0;
            v0.y = alpha * c[mt][nt][1] + bv1;
            v1.x = alpha * c[mt][nt][2] + bv0;
            v1.y = alpha * c[mt][nt][3] + bv1;
            if (beta != 0.f) {
                float2 o0 = *p0, o1 = *p1;
                v0.x += beta * o0.x; v0.y += beta * o0.y;
                v1.x += beta * o1.x; v1.y += beta * o1.y;
            }
            *p0 = v0;
            *p1 = v1;
        }
    }
}

static void gemm(const bf* Ah, const bf* Al, const bf* Bh, const bf* Bl,
                 const float* bias, float* C, int M, int N, int K, int batch,
                 size_t sA, size_t sB, size_t sC, float alpha, float beta)
{
    dim3 grid(N / 128, M / 128, batch), block(256);
    gemm_tc<<<grid, block, GEMM_SMEM>>>(Ah, Al, Bh, Bl, bias, C,
                                        M, N, K, sA, sB, sC, alpha, beta);
}

/* ================= fp32 -> bf16 hi/lo conversions ====================== */
__device__ __forceinline__ void split2(float x, bf& h, bf& l) {
    h = __float2bfloat16(x);
    l = __float2bfloat16(x - __bfloat162float(h));
}

__global__ void split_kernel(const float* __restrict__ in, bf* __restrict__ oh,
                             bf* __restrict__ ol, size_t n4)
{
    size_t i = (size_t)blockIdx.x * blockDim.x + threadIdx.x;
    if (i >= n4) return;
    float4 v = reinterpret_cast<const float4*>(in)[i];
    bf h[4], l[4];
    split2(v.x, h[0], l[0]); split2(v.y, h[1], l[1]);
    split2(v.z, h[2], l[2]); split2(v.w, h[3], l[3]);
    reinterpret_cast<ulonglong1*>(oh)[i] = *reinterpret_cast<ulonglong1*>(h);
    reinterpret_cast<ulonglong1*>(ol)[i] = *reinterpret_cast<ulonglong1*>(l);
}
static void split(const float* in, bf* oh, bf* ol, size_t n)
{
    size_t n4 = n / 4;
    split_kernel<<<(unsigned)((n4 + 255) / 256), 256>>>(in, oh, ol, n4);
}

/* per-batch transpose (R,C)->(C,R) with split */
__global__ void splitT_kernel(const float* __restrict__ in, bf* __restrict__ oh,
                              bf* __restrict__ ol, int R, int Cc)
{
    __shared__ float t[32][33];
    const int b = blockIdx.z;
    const float* ib = in + (size_t)b * R * Cc;
    bf* ohb = oh + (size_t)b * R * Cc;
    bf* olb = ol + (size_t)b * R * Cc;
    const int c0 = blockIdx.x * 32, r0 = blockIdx.y * 32;
#pragma unroll
    for (int k = 0; k < 4; k++)
        t[threadIdx.y + k * 8][threadIdx.x] =
            ib[(size_t)(r0 + threadIdx.y + k * 8) * Cc + c0 + threadIdx.x];
    __syncthreads();
#pragma unroll
    for (int k = 0; k < 4; k++) {
        float v = t[threadIdx.x][threadIdx.y + k * 8];
        bf h, l;
        split2(v, h, l);
        size_t o = (size_t)(c0 + threadIdx.y + k * 8) * R + r0 + threadIdx.x;
        ohb[o] = h;
        olb[o] = l;
    }
}
static void splitT(const float* in, bf* oh, bf* ol, int R, int Cc, int batch)
{
    dim3 grid(Cc / 32, R / 32, batch), block(32, 8);
    splitT_kernel<<<grid, block>>>(in, oh, ol, R, Cc);
}

/* ================= basis fills (bf16 hi/lo direct) ===================== */
__global__ void fill_dft_bf16(bf* __restrict__ ch, bf* __restrict__ cl,
                              bf* __restrict__ sh_, bf* __restrict__ sl)
{
    size_t i = (size_t)blockIdx.x * blockDim.x + threadIdx.x;
    if (i >= (size_t)S_DIM * S_DIM) return;
    int s = (int)(i / S_DIM), t = (int)(i % S_DIM);
    int p = (int)(((long long)s * (long long)t) & (S_DIM - 1));
    float sv, cv;
    sincospif((float)p / 1024.0f, &sv, &cv); /* angle = 2*pi*p/2048 */
    bf h, l;
    split2(cv, h, l); ch[i] = h; cl[i] = l;
    split2(sv, h, l); sh_[i] = h; sl[i] = l;
}

/* Replicate jax's float32 argument arithmetic exactly, then fp32 cos. */
__global__ void fill_dct_bf16(bf* __restrict__ dh, bf* __restrict__ dl,
                              bf* __restrict__ ih, bf* __restrict__ il)
{
    size_t idx = (size_t)blockIdx.x * blockDim.x + threadIdx.x;
    if (idx >= (size_t)S_DIM * S_DIM) return;
    int i = (int)(idx / S_DIM), j = (int)(idx % S_DIM);
    const float PI_F = (float)M_PI;
    const float s0 = 0.02209708691207961f;  /* sqrt(1/2048) */
    const float s1 = 0.03125f;              /* sqrt(2/2048) */
    bf h, l;
    float a  = PI_F * (float)i;
    float b  = a * (float)(2 * j + 1);
    float vD = cosf(b / (float)(2 * S_DIM)) * (i == 0 ? s0 : s1);
    split2(vD, h, l); dh[idx] = h; dl[idx] = l;
    float a2 = PI_F * (float)j;
    float b2 = a2 * (float)(2 * i + 1);
    float vI = cosf(b2 / (float)(2 * S_DIM)) * (j == 0 ? s0 : s1);
    split2(vI, h, l); ih[idx] = h; il[idx] = l;
}

/* ================= small fused ops (unchanged numerics) ================ */
__global__ void __launch_bounds__(512) conv1d_kernel(
    const float* __restrict__ x, const float* __restrict__ Wc,
    const float* __restrict__ bc, float* __restrict__ out)
{
    __shared__ float xs[3 * E_DIM];
    int bs = blockIdx.x;
    int b = bs >> 11;
    int s = bs & 2047;
    for (int i = threadIdx.x; i < 3 * E_DIM; i += 512) {
        int tap = i >> 10;
        int e = i & 1023;
        int sp = s + tap - 1;
        xs[i] = (sp >= 0 && sp < S_DIM) ? x[((size_t)b * S_DIM + sp) * E_DIM + e] : 0.f;
    }
    __syncthreads();
    int c = threadIdx.x >> 5, lane = threadIdx.x & 31;
    const float* w = Wc + (size_t)c * E_DIM * 3;
    float acc = 0.f;
    for (int e = lane; e < E_DIM; e += 32) {
        float x0 = xs[e], x1 = xs[E_DIM + e], x2 = xs[2 * E_DIM + e];
        acc += w[e * 3 + 0] * x0 + w[e * 3 + 1] * x1 + w[e * 3 + 2] * x2;
    }
    acc = warpReduceSum(acc);
    if (lane == 0) out[(size_t)bs * C_DIM + c] = acc + bc[c];
}

__global__ void fweights_kernel(const float* __restrict__ F, float* __restrict__ fw)
{
    int e = blockIdx.x * blockDim.x + threadIdx.x;
    if (e >= E_DIM) return;
    float v[C_DIM], m = -3.4e38f;
#pragma unroll
    for (int c = 0; c < C_DIM; c++) { v[c] = F[c * E_DIM + e]; m = fmaxf(m, v[c]); }
    float s = 0.f;
#pragma unroll
    for (int c = 0; c < C_DIM; c++) { v[c] = expf(v[c] - m); s += v[c]; }
    float inv = 1.f / s;
#pragma unroll
    for (int c = 0; c < C_DIM; c++) fw[c * E_DIM + e] = v[c] * inv;
}

__global__ void mix_kernel(const float* __restrict__ ch, const float* __restrict__ fw,
                           float* __restrict__ out)
{
    size_t i = (size_t)blockIdx.x * blockDim.x + threadIdx.x;
    if (i >= (size_t)BS_DIM * E_DIM) return;
    int e = (int)(i & 1023);
    size_t bs = i >> 10;
    const float* cr = ch + bs * C_DIM;
    float a = 0.f;
#pragma unroll
    for (int c = 0; c < C_DIM; c++) a += cr[c] * fw[c * E_DIM + e];
    out[i] = a;
}

__global__ void softmax_rows_real(float* __restrict__ Sc, int cols, float scale)
{
    float* row = Sc + (size_t)blockIdx.x * cols;
    int tid = threadIdx.x;
    float m = -3.4e38f;
    for (int i = tid; i < cols; i += blockDim.x) m = fmaxf(m, row[i]);
    m = blockReduceMax(m);
    float s = 0.f;
    for (int i = tid; i < cols; i += blockDim.x) {
        float p = expf((row[i] - m) * scale);
        row[i] = p;
        s += p;
    }
    s = blockReduceSum(s);
    float inv = 1.f / s;
    for (int i = tid; i < cols; i += blockDim.x) row[i] *= inv;
}

__global__ void softmax_rows_complex(float* __restrict__ Sr, float* __restrict__ Si,
                                     int cols, float scale)
{
    size_t off = (size_t)blockIdx.x * cols;
    float* rr = Sr + off;
    float* ri = Si + off;
    int tid = threadIdx.x;
    float m = -3.4e38f;
    for (int i = tid; i < cols; i += blockDim.x) m = fmaxf(m, rr[i]);
    m = blockReduceMax(m);
    float s = 0.f;
    for (int i = tid; i < cols; i += blockDim.x) {
        float ar = rr[i], ai = ri[i];
        float p = expf((ar - m) * scale);
        s += p;
        float mag = sqrtf(ar * ar + ai * ai);
        float ur, ui;
        if (mag > 0.f) { ur = ar / mag; ui = ai / mag; }
        else           { ur = 1.f;      ui = 0.f;      }
        rr[i] = p * ur;
        ri[i] = p * ui;
    }
    s = blockReduceSum(s);
    float inv = 1.f / s;
    for (int i = tid; i < cols; i += blockDim.x) { rr[i] *= inv; ri[i] *= inv; }
}

__global__ void haar_level_kernel(const float* __restrict__ cur, float* __restrict__ nxt,
                                  float* __restrict__ sbuf, int L)
{
    int half = L >> 1;
    size_t total = (size_t)B_DIM * half * E_DIM;
    size_t i = (size_t)blockIdx.x * blockDim.x + threadIdx.x;
    if (i >= total) return;
    int e = (int)(i % E_DIM);
    size_t t = i / E_DIM;
    int j = (int)(t % half);
    int b = (int)(t / half);
    const float SQ2F = 1.41421356237309515f;
    float ev = cur[((size_t)b * L + 2 * j) * E_DIM + e];
    float ov = cur[((size_t)b * L + 2 * j + 1) * E_DIM + e];
    sbuf[((size_t)b * S_DIM + half + j) * E_DIM + e] = (ev - ov) / SQ2F;
    float ap = (ev + ov) / SQ2F;
    nxt[((size_t)b * half + j) * E_DIM + e] = ap;
    if (half == 1) sbuf[((size_t)b * S_DIM) * E_DIM + e] = ap;
}

__global__ void stack3_bf16(const float* __restrict__ f, const float* __restrict__ w,
                            const float* __restrict__ c, bf* __restrict__ xh,
                            bf* __restrict__ xl)
{
    size_t i = (size_t)blockIdx.x * blockDim.x + threadIdx.x;
    if (i >= 3 * (size_t)BS_DIM * E_DIM) return;
    size_t e = i % E_DIM;
    size_t t = i / E_DIM;
    size_t d = t % 3, bs = t / 3;
    const float* src = (d == 0) ? f : ((d == 1) ? w : c);
    bf h, l;
    split2(src[bs * E_DIM + e], h, l);
    xh[i] = h;
    xl[i] = l;
}

__global__ void mha_small_attn(const float* __restrict__ qkv, float* __restrict__ out)
{
    int gw = (int)(((size_t)blockIdx.x * blockDim.x + threadIdx.x) >> 5);
    int lane = threadIdx.x & 31;
    if (gw >= BS_DIM * 16) return;
    int g = gw >> 4, h = gw & 15;
    const float* base = qkv + (size_t)g * 3 * 3072 + h * 64;
    float q[3][2], k[3][2], v[3][2];
#pragma unroll
    for (int l = 0; l < 3; l++) {
        q[l][0] = base[(size_t)l * 3072 + lane];
        q[l][1] = base[(size_t)l * 3072 + lane + 32];
        k[l][0] = base[(size_t)l * 3072 + 1024 + lane];
        k[l][1] = base[(size_t)l * 3072 + 1024 + lane + 32];
        v[l][0] = base[(size_t)l * 3072 + 2048 + lane];
        v[l][1] = base[(size_t)l * 3072 + 2048 + lane + 32];
    }
    float sc[3][3];
#pragma unroll
    for (int l = 0; l < 3; l++)
#pragma unroll
        for (int m = 0; m < 3; m++) {
            float t = q[l][0] * k[m][0] + q[l][1] * k[m][1];
#pragma unroll
            for (int o = 16; o; o >>= 1) t += __shfl_xor_sync(0xffffffffu, t, o);
            sc[l][m] = t * 0.125f;
        }
    float a[3][3];
#pragma unroll
    for (int l = 0; l < 3; l++) {
        float m0 = fmaxf(sc[l][0], fmaxf(sc[l][1], sc[l][2]));
        float e0 = expf(sc[l][0] - m0);
        float e1 = expf(sc[l][1] - m0);
        float e2 = expf(sc[l][2] - m0);
        float s = e0 + e1 + e2;
        a[l][0] = e0 / s; a[l][1] = e1 / s; a[l][2] = e2 / s;
    }
    float* ob = out + (size_t)g * 3 * 1024 + h * 64;
#pragma unroll
    for (int l = 0; l < 3; l++) {
        float o0 = a[l][0] * v[0][0] + a[l][1] * v[1][0] + a[l][2] * v[2][0];
        float o1 = a[l][0] * v[0][1] + a[l][1] * v[1][1] + a[l][2] * v[2][1];
        ob[(size_t)l * 1024 + lane] = o0;
        ob[(size_t)l * 1024 + lane + 32] = o1;
    }
}

/* ================= orchestration ======================================= */
extern "C" void kernel_launch(void* const* d_in, const int* in_sizes, int n_in,
                              void* d_out, int out_size)
{
    (void)in_sizes; (void)n_in; (void)out_size;
    const float* query  = (const float*)d_in[0];
    const float* Wp_f   = (const float*)d_in[1];
    const float* bp_f   = (const float*)d_in[2];
    const float* Wc_f   = (const float*)d_in[3];
    const float* bc_f   = (const float*)d_in[4];
    const float* Ff     = (const float*)d_in[5];
    const float* Wp_w   = (const float*)d_in[6];
    const float* bp_w   = (const float*)d_in[7];
    const float* Wc_w   = (const float*)d_in[8];
    const float* bc_w   = (const float*)d_in[9];
    const float* Fw     = (const float*)d_in[10];
    const float* Wp_c   = (const float*)d_in[11];
    const float* bp_c   = (const float*)d_in[12];
    const float* Wc_c   = (const float*)d_in[13];
    const float* bc_c   = (const float*)d_in[14];
    const float* Fc     = (const float*)d_in[15];
    const float* mha_iw = (const float*)d_in[16];
    const float* mha_ib = (const float*)d_in[17];
    const float* mha_ow = (const float*)d_in[18];
    const float* mha_ob = (const float*)d_in[19];
    const float* fus_W  = (const float*)d_in[20];
    const float* fus_b  = (const float*)d_in[21];
    float* out = (float*)d_out;

    cudaFuncSetAttribute(gemm_tc, cudaFuncAttributeMaxDynamicSharedMemorySize, GEMM_SMEM);

    float* A = nullptr;
    bf* Z = nullptr;
    cudaGetSymbolAddress((void**)&A, g_arena);
    cudaGetSymbolAddress((void**)&Z, g_bfarena);

    /* fp32 scratch */
    float* xd    = A + 0 * BSE;
    float* sr    = A + 1 * BSE;
    float* si    = A + 2 * BSE;
    float* chr   = A + 3 * BSE;
    float* chi   = A + 4 * BSE;
    float* or_   = A + 5 * BSE;
    float* oi    = A + 6 * BSE;
    float* outf  = A + 7 * BSE;
    float* outw  = A + 8 * BSE;
    float* outc  = A + 9 * BSE;
    float* scr   = A + 10 * BSE;  /* 2 units */
    float* sci   = A + 12 * BSE;  /* 2 units */
    float* qkv   = A + 14 * BSE;  /* 9 units */
    float* att   = A + 23 * BSE;  /* 3 units */
    float* corr  = A + 26 * BSE;  /* 3 units */
    float* haar0 = A + 29 * BSE;
    float* haar1 = A + 30 * BSE;
    float* chtr  = A + 31 * BSE;
    float* chti  = A + 31 * BSE + 65536;
    float* fwbuf = A + 31 * BSE + 2 * 65536;

    /* bf16 scratch (hi/lo pairs) */
    bf* cos_h  = Z + 0 * BF_UNIT;  bf* cos_l  = Z + 1 * BF_UNIT;
    bf* sin_h  = Z + 2 * BF_UNIT;  bf* sin_l  = Z + 3 * BF_UNIT;
    bf* dctD_h = Z + 4 * BF_UNIT;  bf* dctD_l = Z + 5 * BF_UNIT;
    bf* dctI_h = Z + 6 * BF_UNIT;  bf* dctI_l = Z + 7 * BF_UNIT;
    bf* q_h    = Z + 8 * BF_UNIT;  bf* q_l    = Z + 9 * BF_UNIT;
    bf* w_h    = Z + 10 * BF_UNIT; bf* w_l    = Z + 13 * BF_UNIT;
    bf* xdT_h  = Z + 16 * BF_UNIT; bf* xdT_l  = Z + 17 * BF_UNIT;
    bf* chr_h  = Z + 18 * BF_UNIT; bf* chr_l  = Z + 19 * BF_UNIT;
    bf* chrT_h = Z + 20 * BF_UNIT; bf* chrT_l = Z + 21 * BF_UNIT;
    bf* chi_h  = Z + 22 * BF_UNIT; bf* chi_l  = Z + 23 * BF_UNIT;
    bf* chiT_h = Z + 24 * BF_UNIT; bf* chiT_l = Z + 25 * BF_UNIT;
    bf* scr_h  = Z + 26 * BF_UNIT; bf* scr_l  = Z + 28 * BF_UNIT;
    bf* sci_h  = Z + 30 * BF_UNIT; bf* sci_l  = Z + 32 * BF_UNIT;
    bf* orT_h  = Z + 34 * BF_UNIT; bf* orT_l  = Z + 35 * BF_UNIT;
    bf* oiT_h  = Z + 36 * BF_UNIT; bf* oiT_l  = Z + 37 * BF_UNIT;
    bf* xstk_h = Z + 38 * BF_UNIT; bf* xstk_l = Z + 41 * BF_UNIT;
    bf* att_h  = Z + 44 * BF_UNIT; bf* att_l  = Z + 47 * BF_UNIT;
    bf* corr_h = Z + 50 * BF_UNIT; bf* corr_l = Z + 53 * BF_UNIT;

    const float inv_sqE = 1.f / 32.f;
    const int NB_MIX = (int)((BSE + 255) / 256);

    fill_dft_bf16<<<(unsigned)((SS + 255) / 256), 256>>>(cos_h, cos_l, sin_h, sin_l);
    fill_dct_bf16<<<(unsigned)((SS + 255) / 256), 256>>>(dctD_h, dctD_l, dctI_h, dctI_l);
    split(query, q_h, q_l, BSE);

    /* ============ Fourier ============ */
    split(Wp_f, w_h, w_l, (size_t)E_DIM * E_DIM);
    gemm(q_h, q_l, w_h, w_l, bp_f, xd, BS_DIM, E_DIM, E_DIM, 1, 0, 0, 0, 1.f, 0.f);
    splitT(xd, xdT_h, xdT_l, S_DIM, E_DIM, B_DIM);
    gemm(cos_h, cos_l, xdT_h, xdT_l, nullptr, sr, S_DIM, E_DIM, S_DIM, B_DIM, 0, SE, SE, 1.f, 0.f);
    gemm(sin_h, sin_l, xdT_h, xdT_l, nullptr, si, S_DIM, E_DIM, S_DIM, B_DIM, 0, SE, SE, -1.f, 0.f);
    conv1d_kernel<<<BS_DIM, 512>>>(sr, Wc_f, bc_f, chtr);
    conv1d_kernel<<<BS_DIM, 512>>>(si, Wc_f, bc_f, chti);
    fweights_kernel<<<4, 256>>>(Ff, fwbuf);
    mix_kernel<<<NB_MIX, 256>>>(chtr, fwbuf, chr);
    mix_kernel<<<NB_MIX, 256>>>(chti, fwbuf, chi);
    split(chr, chr_h, chr_l, BSE);
    split(chi, chi_h, chi_l, BSE);
    splitT(chr, chrT_h, chrT_l, S_DIM, E_DIM, B_DIM);
    splitT(chi, chiT_h, chiT_l, S_DIM, E_DIM, B_DIM);
    /* complex scores (transB natural: B = ch itself) */
    gemm(chr_h, chr_l, chr_h, chr_l, nullptr, scr, S_DIM, S_DIM, E_DIM, B_DIM, SE, SE, SS, 1.f, 0.f);
    gemm(chi_h, chi_l, chi_h, chi_l, nullptr, scr, S_DIM, S_DIM, E_DIM, B_DIM, SE, SE, SS, -1.f, 1.f);
    gemm(chr_h, chr_l, chi_h, chi_l, nullptr, sci, S_DIM, S_DIM, E_DIM, B_DIM, SE, SE, SS, 1.f, 0.f);
    gemm(chi_h, chi_l, chr_h, chr_l, nullptr, sci, S_DIM, S_DIM, E_DIM, B_DIM, SE, SE, SS, 1.f, 1.f);
    softmax_rows_complex<<<BS_DIM, 256>>>(scr, sci, S_DIM, inv_sqE);
    split(scr, scr_h, scr_l, 2 * SS);
    split(sci, sci_h, sci_l, 2 * SS);
    /* out = cw @ v (complex) — B operands are transposed ch */
    gemm(scr_h, scr_l, chrT_h, chrT_l, nullptr, or_, S_DIM, E_DIM, S_DIM, B_DIM, SS, SE, SE, 1.f, 0.f);
    gemm(sci_h, sci_l, chiT_h, chiT_l, nullptr, or_, S_DIM, E_DIM, S_DIM, B_DIM, SS, SE, SE, -1.f, 1.f);
    gemm(scr_h, scr_l, chiT_h, chiT_l, nullptr, oi, S_DIM, E_DIM, S_DIM, B_DIM, SS, SE, SE, 1.f, 0.f);
    gemm(sci_h, sci_l, chrT_h, chrT_l, nullptr, oi, S_DIM, E_DIM, S_DIM, B_DIM, SS, SE, SE, 1.f, 1.f);
    splitT(or_, orT_h, orT_l, S_DIM, E_DIM, B_DIM);
    splitT(oi, oiT_h, oiT_l, S_DIM, E_DIM, B_DIM);
    gemm(cos_h, cos_l, orT_h, orT_l, nullptr, outf, S_DIM, E_DIM, S_DIM, B_DIM, 0, SE, SE,
         1.f / (float)S_DIM, 0.f);
    gemm(sin_h, sin_l, oiT_h, oiT_l, nullptr, outf, S_DIM, E_DIM, S_DIM, B_DIM, 0, SE, SE,
         -1.f / (float)S_DIM, 1.f);

    /* ============ Wavelet ============ */
    split(Wp_w, w_h, w_l, (size_t)E_DIM * E_DIM);
    gemm(q_h, q_l, w_h, w_l, bp_w, xd, BS_DIM, E_DIM, E_DIM, 1, 0, 0, 0, 1.f, 0.f);
    {
        const float* cur = xd;
        float* nx = haar0;
        for (int L = S_DIM; L >= 2; L >>= 1) {
            size_t tot = (size_t)B_DIM * (L >> 1) * E_DIM;
            haar_level_kernel<<<(unsigned)((tot + 255) / 256), 256>>>(cur, nx, sr, L);
            cur = nx;
            nx = (nx == haar0) ? haar1 : haar0;
        }
    }
    conv1d_kernel<<<BS_DIM, 512>>>(sr, Wc_w, bc_w, chtr);
    fweights_kernel<<<4, 256>>>(Fw, fwbuf);
    mix_kernel<<<NB_MIX, 256>>>(chtr, fwbuf, chr);
    split(chr, chr_h, chr_l, BSE);
    splitT(chr, chrT_h, chrT_l, S_DIM, E_DIM, B_DIM);
    gemm(chr_h, chr_l, chr_h, chr_l, nullptr, scr, S_DIM, S_DIM, E_DIM, B_DIM, SE, SE, SS, 1.f, 0.f);
    softmax_rows_real<<<BS_DIM, 256>>>(scr, S_DIM, inv_sqE);
    split(scr, scr_h, scr_l, 2 * SS);
    gemm(scr_h, scr_l, chrT_h, chrT_l, nullptr, outw, S_DIM, E_DIM, S_DIM, B_DIM, SS, SE, SE, 1.f, 0.f);

    /* ============ Cosine (DCT) ============ */
    split(Wp_c, w_h, w_l, (size_t)E_DIM * E_DIM);
    gemm(q_h, q_l, w_h, w_l, bp_c, xd, BS_DIM, E_DIM, E_DIM, 1, 0, 0, 0, 1.f, 0.f);
    splitT(xd, xdT_h, xdT_l, S_DIM, E_DIM, B_DIM);
    gemm(dctD_h, dctD_l, xdT_h, xdT_l, nullptr, sr, S_DIM, E_DIM, S_DIM, B_DIM, 0, SE, SE, 1.f, 0.f);
    conv1d_kernel<<<BS_DIM, 512>>>(sr, Wc_c, bc_c, chtr);
    fweights_kernel<<<4, 256>>>(Fc, fwbuf);
    mix_kernel<<<NB_MIX, 256>>>(chtr, fwbuf, chr);
    split(chr, chr_h, chr_l, BSE);
    splitT(chr, chrT_h, chrT_l, S_DIM, E_DIM, B_DIM);
    gemm(chr_h, chr_l, chr_h, chr_l, nullptr, scr, S_DIM, S_DIM, E_DIM, B_DIM, SE, SE, SS, 1.f, 0.f);
    softmax_rows_real<<<BS_DIM, 256>>>(scr, S_DIM, inv_sqE);
    split(scr, scr_h, scr_l, 2 * SS);
    gemm(scr_h, scr_l, chrT_h, chrT_l, nullptr, or_, S_DIM, E_DIM, S_DIM, B_DIM, SS, SE, SE, 1.f, 0.f);
    splitT(or_, orT_h, orT_l, S_DIM, E_DIM, B_DIM);
    gemm(dctI_h, dctI_l, orT_h, orT_l, nullptr, outc, S_DIM, E_DIM, S_DIM, B_DIM, 0, SE, SE, 1.f, 0.f);

    /* ============ cross-domain MHA + fusion ============ */
    stack3_bf16<<<(unsigned)((3 * BSE + 255) / 256), 256>>>(outf, outw, outc, xstk_h, xstk_l);
    split(mha_iw, w_h, w_l, (size_t)3 * E_DIM * E_DIM);
    gemm(xstk_h, xstk_l, w_h, w_l, mha_ib, qkv, T3_DIM, 3 * E_DIM, E_DIM, 1, 0, 0, 0, 1.f, 0.f);
    mha_small_attn<<<(BS_DIM * 16 * 32) / 256, 256>>>(qkv, att);
    split(att, att_h, att_l, 3 * BSE);
    split(mha_ow, w_h, w_l, (size_t)E_DIM * E_DIM);
    gemm(att_h, att_l, w_h, w_l, mha_ob, corr, T3_DIM, E_DIM, E_DIM, 1, 0, 0, 0, 1.f, 0.f);
    split(corr, corr_h, corr_l, 3 * BSE);
    split(fus_W, w_h, w_l, (size_t)3 * E_DIM * E_DIM);
    gemm(corr_h, corr_l, w_h, w_l, fus_b, out, BS_DIM, E_DIM, 3 * E_DIM, 1, 0, 0, 0, 1.f, 0.f);
}

// round 12
// speedup vs baseline: 2.8054x; 1.7195x over previous
#include <cuda_runtime.h>
#include <cuda_bf16.h>
#include <math.h>
#include <stdint.h>

#define B_DIM 2
#define S_DIM 2048
#define E_DIM 1024
#define C_DIM 16
#define BS_DIM (B_DIM * S_DIM)          /* 4096  */
#define T3_DIM (BS_DIM * 3)             /* 12288 */

typedef __nv_bfloat16 bf;

static const size_t BSE = (size_t)BS_DIM * E_DIM;     /* 4194304 */
static const size_t SE  = (size_t)S_DIM * E_DIM;      /* 2097152 */
static const size_t SS  = (size_t)S_DIM * S_DIM;      /* 4194304 */
#define BF_UNIT 4194304ULL

/* fp32 scratch: 32 units (~537 MB) */
__device__ float g_arena[32ULL * BF_UNIT];
/* bf16 scratch: 56 units (~470 MB) */
__device__ bf g_bfarena[56ULL * BF_UNIT];

__device__ __forceinline__ uint32_t smem_to_u32(const void* p) {
    uint32_t a;
    asm("{ .reg .u64 t; cvta.to.shared.u64 t, %1; cvt.u32.u64 %0, t; }"
        : "=r"(a) : "l"(p));
    return a;
}

/* ================= warp-MMA primitives (compute_103-safe) ============== */
__device__ __forceinline__ void ldmx4(uint32_t* r, uint32_t a) {
    asm volatile("ldmatrix.sync.aligned.m8n8.x4.shared.b16 {%0,%1,%2,%3}, [%4];"
                 : "=r"(r[0]), "=r"(r[1]), "=r"(r[2]), "=r"(r[3]) : "r"(a));
}
__device__ __forceinline__ void mma16816(float* c, const uint32_t* a, const uint32_t* b) {
    asm volatile(
        "mma.sync.aligned.m16n8k16.row.col.f32.bf16.bf16.f32 "
        "{%0,%1,%2,%3}, {%4,%5,%6,%7}, {%8,%9}, {%0,%1,%2,%3};"
        : "+f"(c[0]), "+f"(c[1]), "+f"(c[2]), "+f"(c[3])
        : "r"(a[0]), "r"(a[1]), "r"(a[2]), "r"(a[3]), "r"(b[0]), "r"(b[1]));
}
__device__ __forceinline__ void cpa16(uint32_t d, const void* s) {
    asm volatile("cp.async.cg.shared.global [%0], [%1], 16;" :: "r"(d), "l"(s));
}
#define CP_COMMIT() asm volatile("cp.async.commit_group;" ::: "memory")
#define CP_WAIT0()  asm volatile("cp.async.wait_group 0;" ::: "memory")
#define CP_WAIT1()  asm volatile("cp.async.wait_group 1;" ::: "memory")

/* ================= reductions ========================================== */
__device__ __forceinline__ float warpReduceSum(float v) {
#pragma unroll
    for (int o = 16; o; o >>= 1) v += __shfl_xor_sync(0xffffffffu, v, o);
    return v;
}
__device__ __forceinline__ float warpReduceMax(float v) {
#pragma unroll
    for (int o = 16; o; o >>= 1) v = fmaxf(v, __shfl_xor_sync(0xffffffffu, v, o));
    return v;
}
__device__ float blockReduceSum(float v) {
    __shared__ float sh[32];
    __syncthreads();
    int lane = threadIdx.x & 31, wid = threadIdx.x >> 5;
    v = warpReduceSum(v);
    if (lane == 0) sh[wid] = v;
    __syncthreads();
    float r = (threadIdx.x < (blockDim.x >> 5)) ? sh[threadIdx.x] : 0.f;
    r = warpReduceSum(r);
    if (threadIdx.x == 0) sh[0] = r;
    __syncthreads();
    return sh[0];
}
__device__ float blockReduceMax(float v) {
    __shared__ float sh[32];
    __syncthreads();
    int lane = threadIdx.x & 31, wid = threadIdx.x >> 5;
    v = warpReduceMax(v);
    if (lane == 0) sh[wid] = v;
    __syncthreads();
    float r = (threadIdx.x < (blockDim.x >> 5)) ? sh[threadIdx.x] : -3.4e38f;
    r = warpReduceMax(r);
    if (threadIdx.x == 0) sh[0] = r;
    __syncthreads();
    return sh[0];
}

/* ================= unified slice-table split-fp32 GEMM ================= */
/* Per z-slice: C(M,N) = alpha * A(M,K) @ B(N,K)^T + bias[col].           */
struct GSlice {
    const bf* Ah; const bf* Al; const bf* Bh; const bf* Bl;
    float* C; const float* bias; float alpha;
};
struct GTable { GSlice s[6]; };

#define PITCH 144
#define TILE_B (128 * PITCH)
#define STAGE_B (4 * TILE_B)
#define GEMM_SMEM (2 * STAGE_B)          /* 147456 bytes */

__global__ void __launch_bounds__(256) gemm_tc(
    GTable tab, int M, int N, int K)
{
    extern __shared__ char smem[];
    const uint32_t su = smem_to_u32(smem);
    const int tid = threadIdx.x;
    const int lane = tid & 31, wid = tid >> 5;
    const int wm = (wid >> 2) * 64;
    const int wn = (wid & 3) * 32;

    const GSlice sl = tab.s[blockIdx.z];
    float* Cb = sl.C;
    const int bm = blockIdx.y * 128;
    const int bn = blockIdx.x * 128;
    const float alpha = sl.alpha;

    const bf* srcs[4];
    srcs[0] = sl.Ah + (size_t)bm * K;
    srcs[1] = sl.Al + (size_t)bm * K;
    srcs[2] = sl.Bh + (size_t)bn * K;
    srcs[3] = sl.Bl + (size_t)bn * K;

    float c[4][4][4];
#pragma unroll
    for (int i = 0; i < 4; i++)
#pragma unroll
        for (int j = 0; j < 4; j++)
#pragma unroll
            for (int k = 0; k < 4; k++) c[i][j][k] = 0.f;

    const int nch = K / 64;

#define LOADSTAGE(s, k0) do {                                              \
        uint32_t sb_ = su + (s) * STAGE_B;                                 \
        _Pragma("unroll")                                                  \
        for (int t_ = 0; t_ < 4; t_++) {                                   \
            _Pragma("unroll")                                              \
            for (int j_ = 0; j_ < 4; j_++) {                               \
                int idx_ = j_ * 256 + tid;                                 \
                int row_ = idx_ >> 3;                                      \
                int cc_ = idx_ & 7;                                        \
                uint32_t d_ = sb_ + t_ * TILE_B + row_ * PITCH + cc_ * 16; \
                const void* g_ = srcs[t_] + (size_t)row_ * K + (k0) + cc_ * 8; \
                cpa16(d_, g_);                                             \
            }                                                              \
        }                                                                  \
        CP_COMMIT();                                                       \
    } while (0)

    LOADSTAGE(0, 0);

    const int qa = lane >> 3;
    const int ra = lane & 7;
    const int arow = (qa & 1) * 8 + ra;
    const int acol = (qa >> 1) * 16;
    /* B x4 pairing: lanes 0-7: nt0/k0, 8-15: nt0/k8, 16-23: nt1/k0, 24-31: nt1/k8 */
    const int bsub  = lane >> 4;
    const int bhalf = (lane >> 3) & 1;
    const int brow2 = lane & 7;

    for (int i = 0; i < nch; i++) {
        if (i + 1 < nch) { LOADSTAGE((i + 1) & 1, (i + 1) * 64); CP_WAIT1(); }
        else             { CP_WAIT0(); }
        __syncthreads();

        const uint32_t sb = su + (i & 1) * STAGE_B;
#pragma unroll
        for (int kk = 0; kk < 4; kk++) {
            uint32_t fAh[4][4], fAl[4][4], fBh[4][2], fBl[4][2];
#pragma unroll
            for (int mt = 0; mt < 4; mt++) {
                uint32_t a = sb + (wm + mt * 16 + arow) * PITCH + kk * 32 + acol;
                ldmx4(fAh[mt], a);
                ldmx4(fAl[mt], a + TILE_B);
            }
#pragma unroll
            for (int ntp = 0; ntp < 2; ntp++) {
                uint32_t a = sb + 2 * TILE_B +
                             (wn + (ntp * 2 + bsub) * 8 + brow2) * PITCH + kk * 32 + bhalf * 16;
                uint32_t t[4];
                ldmx4(t, a);
                fBh[ntp * 2][0] = t[0]; fBh[ntp * 2][1] = t[1];
                fBh[ntp * 2 + 1][0] = t[2]; fBh[ntp * 2 + 1][1] = t[3];
                ldmx4(t, a + TILE_B);
                fBl[ntp * 2][0] = t[0]; fBl[ntp * 2][1] = t[1];
                fBl[ntp * 2 + 1][0] = t[2]; fBl[ntp * 2 + 1][1] = t[3];
            }
#pragma unroll
            for (int mt = 0; mt < 4; mt++)
#pragma unroll
                for (int nt = 0; nt < 4; nt++) {
                    mma16816(c[mt][nt], fAh[mt], fBh[nt]);
                    mma16816(c[mt][nt], fAh[mt], fBl[nt]);
                    mma16816(c[mt][nt], fAl[mt], fBh[nt]);
                }
        }
        __syncthreads();
    }

    const int g = lane >> 2, t4 = lane & 3;
#pragma unroll
    for (int mt = 0; mt < 4; mt++) {
#pragma unroll
        for (int nt = 0; nt < 4; nt++) {
            const int col = bn + wn + nt * 8 + 2 * t4;
            const int row0 = bm + wm + mt * 16 + g;
            float bv0 = 0.f, bv1 = 0.f;
            if (sl.bias) { bv0 = sl.bias[col]; bv1 = sl.bias[col + 1]; }
            float2 v0, v1;
            v0.x = alpha * c[mt][nt][0] + bv0;
            v0.y = alpha * c[mt][nt][1] + bv1;
            v1.x = alpha * c[mt][nt][2] + bv0;
            v1.y = alpha * c[mt][nt][3] + bv1;
            *reinterpret_cast<float2*>(&Cb[(size_t)row0 * N + col]) = v0;
            *reinterpret_cast<float2*>(&Cb[(size_t)(row0 + 8) * N + col]) = v1;
        }
    }
}

static void gemm1(const bf* Ah, const bf* Al, const bf* Bh, const bf* Bl,
                  const float* bias, float* C, int M, int N, int K)
{
    GTable t{};
    t.s[0] = {Ah, Al, Bh, Bl, C, bias, 1.f};
    dim3 grid(N / 128, M / 128, 1), block(256);
    gemm_tc<<<grid, block, GEMM_SMEM>>>(t, M, N, K);
}
static void gemmN(const GTable& t, int nz, int M, int N, int K)
{
    dim3 grid(N / 128, M / 128, nz), block(256);
    gemm_tc<<<grid, block, GEMM_SMEM>>>(t, M, N, K);
}

/* ================= fp32 -> bf16 hi/lo conversions ====================== */
__device__ __forceinline__ void split2(float x, bf& h, bf& l) {
    h = __float2bfloat16(x);
    l = __float2bfloat16(x - __bfloat162float(h));
}

__global__ void split_kernel(const float* __restrict__ in, bf* __restrict__ oh,
                             bf* __restrict__ ol, size_t n4)
{
    size_t i = (size_t)blockIdx.x * blockDim.x + threadIdx.x;
    if (i >= n4) return;
    float4 v = reinterpret_cast<const float4*>(in)[i];
    bf h[4], l[4];
    split2(v.x, h[0], l[0]); split2(v.y, h[1], l[1]);
    split2(v.z, h[2], l[2]); split2(v.w, h[3], l[3]);
    reinterpret_cast<ulonglong1*>(oh)[i] = *reinterpret_cast<ulonglong1*>(h);
    reinterpret_cast<ulonglong1*>(ol)[i] = *reinterpret_cast<ulonglong1*>(l);
}
static void split(const float* in, bf* oh, bf* ol, size_t n)
{
    size_t n4 = n / 4;
    split_kernel<<<(unsigned)((n4 + 255) / 256), 256>>>(in, oh, ol, n4);
}

/* per-batch transpose (R,C)->(C,R) with split */
__global__ void splitT_kernel(const float* __restrict__ in, bf* __restrict__ oh,
                              bf* __restrict__ ol, int R, int Cc)
{
    __shared__ float t[32][33];
    const int b = blockIdx.z;
    const float* ib = in + (size_t)b * R * Cc;
    bf* ohb = oh + (size_t)b * R * Cc;
    bf* olb = ol + (size_t)b * R * Cc;
    const int c0 = blockIdx.x * 32, r0 = blockIdx.y * 32;
#pragma unroll
    for (int k = 0; k < 4; k++)
        t[threadIdx.y + k * 8][threadIdx.x] =
            ib[(size_t)(r0 + threadIdx.y + k * 8) * Cc + c0 + threadIdx.x];
    __syncthreads();
#pragma unroll
    for (int k = 0; k < 4; k++) {
        float v = t[threadIdx.x][threadIdx.y + k * 8];
        bf h, l;
        split2(v, h, l);
        size_t o = (size_t)(c0 + threadIdx.y + k * 8) * R + r0 + threadIdx.x;
        ohb[o] = h;
        olb[o] = l;
    }
}
static void splitT(const float* in, bf* oh, bf* ol, int R, int Cc, int batch)
{
    dim3 grid(Cc / 32, R / 32, batch), block(32, 8);
    splitT_kernel<<<grid, block>>>(in, oh, ol, R, Cc);
}

/* 3M attnout combine + transpose + split: Or=T1-T2, Oi=T3-T1-T2 */
__global__ void splitT3_kernel(const float* __restrict__ T1, const float* __restrict__ T2,
                               const float* __restrict__ T3,
                               bf* __restrict__ orh, bf* __restrict__ orl,
                               bf* __restrict__ oih, bf* __restrict__ oil)
{
    __shared__ float tr[32][33], ti[32][33];
    const int b = blockIdx.z;
    const size_t base = (size_t)b * SE;
    const int c0 = blockIdx.x * 32, r0 = blockIdx.y * 32;
#pragma unroll
    for (int k = 0; k < 4; k++) {
        size_t idx = base + (size_t)(r0 + threadIdx.y + k * 8) * E_DIM + c0 + threadIdx.x;
        float a = T1[idx], bb = T2[idx], cc = T3[idx];
        tr[threadIdx.y + k * 8][threadIdx.x] = a - bb;
        ti[threadIdx.y + k * 8][threadIdx.x] = cc - a - bb;
    }
    __syncthreads();
#pragma unroll
    for (int k = 0; k < 4; k++) {
        size_t o = base + (size_t)(c0 + threadIdx.y + k * 8) * S_DIM + r0 + threadIdx.x;
        bf h, l;
        split2(tr[threadIdx.x][threadIdx.y + k * 8], h, l);
        orh[o] = h; orl[o] = l;
        split2(ti[threadIdx.x][threadIdx.y + k * 8], h, l);
        oih[o] = h; oil[o] = l;
    }
}

/* ================= basis fills (bf16 hi/lo direct) ===================== */
__global__ void fill_dft_bf16(bf* __restrict__ ch, bf* __restrict__ cl,
                              bf* __restrict__ sh_, bf* __restrict__ sl)
{
    size_t i = (size_t)blockIdx.x * blockDim.x + threadIdx.x;
    if (i >= (size_t)S_DIM * S_DIM) return;
    int s = (int)(i / S_DIM), t = (int)(i % S_DIM);
    int p = (int)(((long long)s * (long long)t) & (S_DIM - 1));
    float sv, cv;
    sincospif((float)p / 1024.0f, &sv, &cv);
    bf h, l;
    split2(cv, h, l); ch[i] = h; cl[i] = l;
    split2(sv, h, l); sh_[i] = h; sl[i] = l;
}

__global__ void fill_dct_bf16(bf* __restrict__ dh, bf* __restrict__ dl,
                              bf* __restrict__ ih, bf* __restrict__ il)
{
    size_t idx = (size_t)blockIdx.x * blockDim.x + threadIdx.x;
    if (idx >= (size_t)S_DIM * S_DIM) return;
    int i = (int)(idx / S_DIM), j = (int)(idx % S_DIM);
    const float PI_F = (float)M_PI;
    const float s0 = 0.02209708691207961f;
    const float s1 = 0.03125f;
    bf h, l;
    float a  = PI_F * (float)i;
    float b  = a * (float)(2 * j + 1);
    float vD = cosf(b / (float)(2 * S_DIM)) * (i == 0 ? s0 : s1);
    split2(vD, h, l); dh[idx] = h; dl[idx] = l;
    float a2 = PI_F * (float)j;
    float b2 = a2 * (float)(2 * i + 1);
    float vI = cosf(b2 / (float)(2 * S_DIM)) * (j == 0 ? s0 : s1);
    split2(vI, h, l); ih[idx] = h; il[idx] = l;
}

/* ================= conv / mix / softmax / haar ========================= */
__global__ void __launch_bounds__(512) conv1d_kernel(
    const float* __restrict__ x, const float* __restrict__ Wc,
    const float* __restrict__ bc, float* __restrict__ out)
{
    __shared__ float xs[3 * E_DIM];
    int bs = blockIdx.x;
    int b = bs >> 11;
    int s = bs & 2047;
    for (int i = threadIdx.x; i < 3 * E_DIM; i += 512) {
        int tap = i >> 10;
        int e = i & 1023;
        int sp = s + tap - 1;
        xs[i] = (sp >= 0 && sp < S_DIM) ? x[((size_t)b * S_DIM + sp) * E_DIM + e] : 0.f;
    }
    __syncthreads();
    int c = threadIdx.x >> 5, lane = threadIdx.x & 31;
    const float* w = Wc + (size_t)c * E_DIM * 3;
    float acc = 0.f;
    for (int e = lane; e < E_DIM; e += 32) {
        float x0 = xs[e], x1 = xs[E_DIM + e], x2 = xs[2 * E_DIM + e];
        acc += w[e * 3 + 0] * x0 + w[e * 3 + 1] * x1 + w[e * 3 + 2] * x2;
    }
    acc = warpReduceSum(acc);
    if (lane == 0) out[(size_t)bs * C_DIM + c] = acc + bc[c];
}

/* real+imag fused conv: weight rows read once */
__global__ void __launch_bounds__(512) conv1d_c_kernel(
    const float* __restrict__ xr, const float* __restrict__ xi,
    const float* __restrict__ Wc, const float* __restrict__ bc,
    float* __restrict__ outr, float* __restrict__ outi)
{
    __shared__ float xsr[3 * E_DIM];
    __shared__ float xsi[3 * E_DIM];
    int bs = blockIdx.x;
    int b = bs >> 11;
    int s = bs & 2047;
    for (int i = threadIdx.x; i < 3 * E_DIM; i += 512) {
        int tap = i >> 10;
        int e = i & 1023;
        int sp = s + tap - 1;
        bool in = (sp >= 0 && sp < S_DIM);
        size_t gi = ((size_t)b * S_DIM + sp) * E_DIM + e;
        xsr[i] = in ? xr[gi] : 0.f;
        xsi[i] = in ? xi[gi] : 0.f;
    }
    __syncthreads();
    int c = threadIdx.x >> 5, lane = threadIdx.x & 31;
    const float* w = Wc + (size_t)c * E_DIM * 3;
    float ar = 0.f, ai = 0.f;
    for (int e = lane; e < E_DIM; e += 32) {
        float w0 = w[e * 3 + 0], w1 = w[e * 3 + 1], w2 = w[e * 3 + 2];
        ar += w0 * xsr[e] + w1 * xsr[E_DIM + e] + w2 * xsr[2 * E_DIM + e];
        ai += w0 * xsi[e] + w1 * xsi[E_DIM + e] + w2 * xsi[2 * E_DIM + e];
    }
    ar = warpReduceSum(ar);
    ai = warpReduceSum(ai);
    if (lane == 0) {
        outr[(size_t)bs * C_DIM + c] = ar + bc[c];
        outi[(size_t)bs * C_DIM + c] = ai + bc[c];
    }
}

__global__ void fweights_kernel(const float* __restrict__ F, float* __restrict__ fw)
{
    int e = blockIdx.x * blockDim.x + threadIdx.x;
    if (e >= E_DIM) return;
    float v[C_DIM], m = -3.4e38f;
#pragma unroll
    for (int c = 0; c < C_DIM; c++) { v[c] = F[c * E_DIM + e]; m = fmaxf(m, v[c]); }
    float s = 0.f;
#pragma unroll
    for (int c = 0; c < C_DIM; c++) { v[c] = expf(v[c] - m); s += v[c]; }
    float inv = 1.f / s;
#pragma unroll
    for (int c = 0; c < C_DIM; c++) fw[c * E_DIM + e] = v[c] * inv;
}

/* mix real: fp32 + fused split */
__global__ void mix_real_kernel(const float* __restrict__ ch, const float* __restrict__ fw,
                                float* __restrict__ out, bf* __restrict__ oh, bf* __restrict__ ol)
{
    size_t i = (size_t)blockIdx.x * blockDim.x + threadIdx.x;
    if (i >= (size_t)BS_DIM * E_DIM) return;
    int e = (int)(i & 1023);
    size_t bs = i >> 10;
    const float* cr = ch + bs * C_DIM;
    float a = 0.f;
#pragma unroll
    for (int c = 0; c < C_DIM; c++) a += cr[c] * fw[c * E_DIM + e];
    out[i] = a;
    bf h, l;
    split2(a, h, l);
    oh[i] = h; ol[i] = l;
}

/* mix complex: r, i, s=r+i (fp32 for transposes) + fused splits */
__global__ void mix_complex_kernel(
    const float* __restrict__ chr_, const float* __restrict__ chi_,
    const float* __restrict__ fw,
    float* __restrict__ outr, float* __restrict__ outi, float* __restrict__ outs,
    bf* __restrict__ rh, bf* __restrict__ rl, bf* __restrict__ ih2, bf* __restrict__ il2,
    bf* __restrict__ sh2, bf* __restrict__ sl2)
{
    size_t i = (size_t)blockIdx.x * blockDim.x + threadIdx.x;
    if (i >= (size_t)BS_DIM * E_DIM) return;
    int e = (int)(i & 1023);
    size_t bs = i >> 10;
    const float* cr = chr_ + bs * C_DIM;
    const float* ci = chi_ + bs * C_DIM;
    float ar = 0.f, ai = 0.f;
#pragma unroll
    for (int c = 0; c < C_DIM; c++) {
        float w = fw[c * E_DIM + e];
        ar += cr[c] * w;
        ai += ci[c] * w;
    }
    float as = ar + ai;
    outr[i] = ar; outi[i] = ai; outs[i] = as;
    bf h, l;
    split2(ar, h, l); rh[i] = h; rl[i] = l;
    split2(ai, h, l); ih2[i] = h; il2[i] = l;
    split2(as, h, l); sh2[i] = h; sl2[i] = l;
}

/* real softmax: fp32 scores in, bf16 hi/lo weights out (row = 2048) */
__global__ void __launch_bounds__(256) softmax_real_bf16(
    const float* __restrict__ T, bf* __restrict__ oh, bf* __restrict__ ol, float scale)
{
    size_t base = (size_t)blockIdx.x * S_DIM;
    int tid = threadIdx.x;
    float v[8];
    float m = -3.4e38f;
#pragma unroll
    for (int j = 0; j < 8; j++) {
        v[j] = T[base + tid + j * 256];
        m = fmaxf(m, v[j]);
    }
    m = blockReduceMax(m);
    float s = 0.f;
#pragma unroll
    for (int j = 0; j < 8; j++) {
        v[j] = expf((v[j] - m) * scale);
        s += v[j];
    }
    s = blockReduceSum(s);
    float inv = 1.f / s;
#pragma unroll
    for (int j = 0; j < 8; j++) {
        bf h, l;
        split2(v[j] * inv, h, l);
        oh[base + tid + j * 256] = h;
        ol[base + tid + j * 256] = l;
    }
}

/* complex softmax with 3M combine: inputs T1,T2,T3; outputs cwR,cwI,cwR+cwI (bf16 pairs) */
__global__ void __launch_bounds__(256) softmax_c3m(
    const float* __restrict__ T1, const float* __restrict__ T2, const float* __restrict__ T3,
    bf* __restrict__ rh, bf* __restrict__ rl, bf* __restrict__ ih2, bf* __restrict__ il2,
    bf* __restrict__ sh2, bf* __restrict__ sl2, float scale)
{
    size_t base = (size_t)blockIdx.x * S_DIM;
    int tid = threadIdx.x;
    float sr[8], si[8];
    float m = -3.4e38f;
#pragma unroll
    for (int j = 0; j < 8; j++) {
        size_t idx = base + tid + j * 256;
        float a = T1[idx], b = T2[idx], c = T3[idx];
        sr[j] = a - b;
        si[j] = c - a - b;
        m = fmaxf(m, sr[j]);
    }
    m = blockReduceMax(m);
    float s = 0.f;
#pragma unroll
    for (int j = 0; j < 8; j++) {
        float p = expf((sr[j] - m) * scale);
        s += p;
        float mag = sqrtf(sr[j] * sr[j] + si[j] * si[j]);
        float ur, ui;
        if (mag > 0.f) { ur = sr[j] / mag; ui = si[j] / mag; }
        else           { ur = 1.f;         ui = 0.f;         }
        sr[j] = p * ur;
        si[j] = p * ui;
    }
    s = blockReduceSum(s);
    float inv = 1.f / s;
#pragma unroll
    for (int j = 0; j < 8; j++) {
        size_t idx = base + tid + j * 256;
        float r = sr[j] * inv, i2 = si[j] * inv;
        bf h, l;
        split2(r, h, l);      rh[idx] = h;  rl[idx] = l;
        split2(i2, h, l);     ih2[idx] = h; il2[idx] = l;
        split2(r + i2, h, l); sh2[idx] = h; sl2[idx] = l;
    }
}

__global__ void haar_level_kernel(const float* __restrict__ cur, float* __restrict__ nxt,
                                  float* __restrict__ sbuf, int L)
{
    int half = L >> 1;
    size_t total = (size_t)B_DIM * half * E_DIM;
    size_t i = (size_t)blockIdx.x * blockDim.x + threadIdx.x;
    if (i >= total) return;
    int e = (int)(i % E_DIM);
    size_t t = i / E_DIM;
    int j = (int)(t % half);
    int b = (int)(t / half);
    const float SQ2F = 1.41421356237309515f;
    float ev = cur[((size_t)b * L + 2 * j) * E_DIM + e];
    float ov = cur[((size_t)b * L + 2 * j + 1) * E_DIM + e];
    sbuf[((size_t)b * S_DIM + half + j) * E_DIM + e] = (ev - ov) / SQ2F;
    float ap = (ev + ov) / SQ2F;
    nxt[((size_t)b * half + j) * E_DIM + e] = ap;
    if (half == 1) sbuf[((size_t)b * S_DIM) * E_DIM + e] = ap;
}

/* stack: f = P1+P2 (pre-scaled IDFT partials), w = outw, c = outc */
__global__ void stack3_bf16(const float* __restrict__ P1, const float* __restrict__ P2,
                            const float* __restrict__ w, const float* __restrict__ c,
                            bf* __restrict__ xh, bf* __restrict__ xl)
{
    size_t i = (size_t)blockIdx.x * blockDim.x + threadIdx.x;
    if (i >= 3 * (size_t)BS_DIM * E_DIM) return;
    size_t e = i % E_DIM;
    size_t t = i / E_DIM;
    size_t d = t % 3, bs = t / 3;
    size_t src = bs * E_DIM + e;
    float v;
    if (d == 0)      v = P1[src] + P2[src];
    else if (d == 1) v = w[src];
    else             v = c[src];
    bf h, l;
    split2(v, h, l);
    xh[i] = h;
    xl[i] = l;
}

__global__ void mha_small_attn(const float* __restrict__ qkv, float* __restrict__ out)
{
    int gw = (int)(((size_t)blockIdx.x * blockDim.x + threadIdx.x) >> 5);
    int lane = threadIdx.x & 31;
    if (gw >= BS_DIM * 16) return;
    int g = gw >> 4, h = gw & 15;
    const float* base = qkv + (size_t)g * 3 * 3072 + h * 64;
    float q[3][2], k[3][2], v[3][2];
#pragma unroll
    for (int l = 0; l < 3; l++) {
        q[l][0] = base[(size_t)l * 3072 + lane];
        q[l][1] = base[(size_t)l * 3072 + lane + 32];
        k[l][0] = base[(size_t)l * 3072 + 1024 + lane];
        k[l][1] = base[(size_t)l * 3072 + 1024 + lane + 32];
        v[l][0] = base[(size_t)l * 3072 + 2048 + lane];
        v[l][1] = base[(size_t)l * 3072 + 2048 + lane + 32];
    }
    float sc[3][3];
#pragma unroll
    for (int l = 0; l < 3; l++)
#pragma unroll
        for (int m = 0; m < 3; m++) {
            float t = q[l][0] * k[m][0] + q[l][1] * k[m][1];
#pragma unroll
            for (int o = 16; o; o >>= 1) t += __shfl_xor_sync(0xffffffffu, t, o);
            sc[l][m] = t * 0.125f;
        }
    float a[3][3];
#pragma unroll
    for (int l = 0; l < 3; l++) {
        float m0 = fmaxf(sc[l][0], fmaxf(sc[l][1], sc[l][2]));
        float e0 = expf(sc[l][0] - m0);
        float e1 = expf(sc[l][1] - m0);
        float e2 = expf(sc[l][2] - m0);
        float s = e0 + e1 + e2;
        a[l][0] = e0 / s; a[l][1] = e1 / s; a[l][2] = e2 / s;
    }
    float* ob = out + (size_t)g * 3 * 1024 + h * 64;
#pragma unroll
    for (int l = 0; l < 3; l++) {
        float o0 = a[l][0] * v[0][0] + a[l][1] * v[1][0] + a[l][2] * v[2][0];
        float o1 = a[l][0] * v[0][1] + a[l][1] * v[1][1] + a[l][2] * v[2][1];
        ob[(size_t)l * 1024 + lane] = o0;
        ob[(size_t)l * 1024 + lane + 32] = o1;
    }
}

/* ================= orchestration ======================================= */
extern "C" void kernel_launch(void* const* d_in, const int* in_sizes, int n_in,
                              void* d_out, int out_size)
{
    (void)in_sizes; (void)n_in; (void)out_size;
    const float* query  = (const float*)d_in[0];
    const float* Wp_f   = (const float*)d_in[1];
    const float* bp_f   = (const float*)d_in[2];
    const float* Wc_f   = (const float*)d_in[3];
    const float* bc_f   = (const float*)d_in[4];
    const float* Ff     = (const float*)d_in[5];
    const float* Wp_w   = (const float*)d_in[6];
    const float* bp_w   = (const float*)d_in[7];
    const float* Wc_w   = (const float*)d_in[8];
    const float* bc_w   = (const float*)d_in[9];
    const float* Fw     = (const float*)d_in[10];
    const float* Wp_c   = (const float*)d_in[11];
    const float* bp_c   = (const float*)d_in[12];
    const float* Wc_c   = (const float*)d_in[13];
    const float* bc_c   = (const float*)d_in[14];
    const float* Fc     = (const float*)d_in[15];
    const float* mha_iw = (const float*)d_in[16];
    const float* mha_ib = (const float*)d_in[17];
    const float* mha_ow = (const float*)d_in[18];
    const float* mha_ob = (const float*)d_in[19];
    const float* fus_W  = (const float*)d_in[20];
    const float* fus_b  = (const float*)d_in[21];
    float* out = (float*)d_out;

    cudaFuncSetAttribute(gemm_tc, cudaFuncAttributeMaxDynamicSharedMemorySize, GEMM_SMEM);

    float* A = nullptr;
    bf* Z = nullptr;
    cudaGetSymbolAddress((void**)&A, g_arena);
    cudaGetSymbolAddress((void**)&Z, g_bfarena);

    /* fp32 units */
    float* xd    = A + 0 * BSE;
    float* sr    = A + 1 * BSE;
    float* si    = A + 2 * BSE;
    float* chr   = A + 3 * BSE;
    float* chi   = A + 4 * BSE;
    float* chs   = A + 5 * BSE;
    float* Ts1   = A + 6 * BSE;   /* 2 units; also haar ping-pong */
    float* Ts2   = A + 8 * BSE;   /* 2 units; also chtr/chti/fwbuf overlay */
    float* Ts3   = A + 10 * BSE;  /* 2 units */
    float* Ta1   = A + 12 * BSE;
    float* Ta2   = A + 13 * BSE;
    float* Ta3   = A + 14 * BSE;
    float* P1    = A + 15 * BSE;
    float* P2    = A + 16 * BSE;
    float* outw  = A + 17 * BSE;
    float* outc  = A + 18 * BSE;
    float* qkv   = A + 19 * BSE;  /* 9 units */
    float* att   = A + 28 * BSE;  /* 3 units */
    float* corr  = A + 6 * BSE;   /* reuse Ts1..Ts2 (3 units, free at MHA) */
    float* haar0 = A + 6 * BSE;
    float* haar1 = A + 7 * BSE;
    float* chtr  = A + 8 * BSE;
    float* chti  = A + 8 * BSE + 65536;
    float* fwbuf = A + 8 * BSE + 2 * 65536;

    /* bf16 units */
    bf* cos_h  = Z + 0 * BF_UNIT;  bf* cos_l  = Z + 1 * BF_UNIT;
    bf* sin_h  = Z + 2 * BF_UNIT;  bf* sin_l  = Z + 3 * BF_UNIT;
    bf* dctD_h = Z + 4 * BF_UNIT;  bf* dctD_l = Z + 5 * BF_UNIT;
    bf* dctI_h = Z + 6 * BF_UNIT;  bf* dctI_l = Z + 7 * BF_UNIT;
    bf* q_h    = Z + 8 * BF_UNIT;  bf* q_l    = Z + 9 * BF_UNIT;
    bf* w_h    = Z + 10 * BF_UNIT; bf* w_l    = Z + 13 * BF_UNIT; /* 3 units each */
    bf* xdT_h  = Z + 16 * BF_UNIT; bf* xdT_l  = Z + 17 * BF_UNIT;
    bf* chr_h  = Z + 18 * BF_UNIT; bf* chr_l  = Z + 19 * BF_UNIT;
    bf* chi_h  = Z + 20 * BF_UNIT; bf* chi_l  = Z + 21 * BF_UNIT;
    bf* chs_h  = Z + 22 * BF_UNIT; bf* chs_l  = Z + 23 * BF_UNIT;
    bf* chrT_h = Z + 24 * BF_UNIT; bf* chrT_l = Z + 25 * BF_UNIT;
    bf* chiT_h = Z + 26 * BF_UNIT; bf* chiT_l = Z + 27 * BF_UNIT;
    bf* chsT_h = Z + 28 * BF_UNIT; bf* chsT_l = Z + 29 * BF_UNIT;
    bf* Sr_h   = Z + 30 * BF_UNIT; bf* Sr_l   = Z + 32 * BF_UNIT; /* 2 units each */
    bf* Si_h   = Z + 34 * BF_UNIT; bf* Si_l   = Z + 36 * BF_UNIT;
    bf* Ss_h   = Z + 38 * BF_UNIT; bf* Ss_l   = Z + 40 * BF_UNIT;
    bf* orT_h  = Z + 42 * BF_UNIT; bf* orT_l  = Z + 43 * BF_UNIT;
    bf* oiT_h  = Z + 44 * BF_UNIT; bf* oiT_l  = Z + 45 * BF_UNIT;
    bf* xstk_h = Z + 46 * BF_UNIT; bf* xstk_l = Z + 49 * BF_UNIT; /* 3 units each */
    bf* att_h  = Z + 30 * BF_UNIT; bf* att_l  = Z + 33 * BF_UNIT; /* reuse S* */
    bf* corr_h = Z + 36 * BF_UNIT; bf* corr_l = Z + 39 * BF_UNIT;

    const float inv_sqE = 1.f / 32.f;
    const float invS = 1.f / (float)S_DIM;
    const int NB_MIX = (int)((BSE + 255) / 256);

    fill_dft_bf16<<<(unsigned)((SS + 255) / 256), 256>>>(cos_h, cos_l, sin_h, sin_l);
    fill_dct_bf16<<<(unsigned)((SS + 255) / 256), 256>>>(dctD_h, dctD_l, dctI_h, dctI_l);
    split(query, q_h, q_l, BSE);

    GTable t;

    /* ============ Fourier ============ */
    split(Wp_f, w_h, w_l, (size_t)E_DIM * E_DIM);
    gemm1(q_h, q_l, w_h, w_l, bp_f, xd, BS_DIM, E_DIM, E_DIM);
    splitT(xd, xdT_h, xdT_l, S_DIM, E_DIM, B_DIM);
    /* DFT: z=4 — sr = cos@xdT, si = -sin@xdT, per batch */
    t = GTable{};
    t.s[0] = {cos_h, cos_l, xdT_h,      xdT_l,      sr,      nullptr, 1.f};
    t.s[1] = {cos_h, cos_l, xdT_h + SE, xdT_l + SE, sr + SE, nullptr, 1.f};
    t.s[2] = {sin_h, sin_l, xdT_h,      xdT_l,      si,      nullptr, -1.f};
    t.s[3] = {sin_h, sin_l, xdT_h + SE, xdT_l + SE, si + SE, nullptr, -1.f};
    gemmN(t, 4, S_DIM, E_DIM, S_DIM);
    conv1d_c_kernel<<<BS_DIM, 512>>>(sr, si, Wc_f, bc_f, chtr, chti);
    fweights_kernel<<<4, 256>>>(Ff, fwbuf);
    mix_complex_kernel<<<NB_MIX, 256>>>(chtr, chti, fwbuf, chr, chi, chs,
                                        chr_h, chr_l, chi_h, chi_l, chs_h, chs_l);
    splitT(chr, chrT_h, chrT_l, S_DIM, E_DIM, B_DIM);
    splitT(chi, chiT_h, chiT_l, S_DIM, E_DIM, B_DIM);
    splitT(chs, chsT_h, chsT_l, S_DIM, E_DIM, B_DIM);
    /* 3M scores: z=6 — T1=chr@chr', T2=chi@chi', T3=chs@chs' */
    t = GTable{};
    t.s[0] = {chr_h,      chr_l,      chr_h,      chr_l,      Ts1,      nullptr, 1.f};
    t.s[1] = {chr_h + SE, chr_l + SE, chr_h + SE, chr_l + SE, Ts1 + SS, nullptr, 1.f};
    t.s[2] = {chi_h,      chi_l,      chi_h,      chi_l,      Ts2,      nullptr, 1.f};
    t.s[3] = {chi_h + SE, chi_l + SE, chi_h + SE, chi_l + SE, Ts2 + SS, nullptr, 1.f};
    t.s[4] = {chs_h,      chs_l,      chs_h,      chs_l,      Ts3,      nullptr, 1.f};
    t.s[5] = {chs_h + SE, chs_l + SE, chs_h + SE, chs_l + SE, Ts3 + SS, nullptr, 1.f};
    gemmN(t, 6, S_DIM, S_DIM, E_DIM);
    softmax_c3m<<<2 * S_DIM, 256>>>(Ts1, Ts2, Ts3, Sr_h, Sr_l, Si_h, Si_l, Ss_h, Ss_l, inv_sqE);
    /* 3M attn-out: z=6 — T1=Sr@chrT', T2=Si@chiT', T3=Ss@chsT' */
    t = GTable{};
    t.s[0] = {Sr_h,      Sr_l,      chrT_h,      chrT_l,      Ta1,      nullptr, 1.f};
    t.s[1] = {Sr_h + SS, Sr_l + SS, chrT_h + SE, chrT_l + SE, Ta1 + SE, nullptr, 1.f};
    t.s[2] = {Si_h,      Si_l,      chiT_h,      chiT_l,      Ta2,      nullptr, 1.f};
    t.s[3] = {Si_h + SS, Si_l + SS, chiT_h + SE, chiT_l + SE, Ta2 + SE, nullptr, 1.f};
    t.s[4] = {Ss_h,      Ss_l,      chsT_h,      chsT_l,      Ta3,      nullptr, 1.f};
    t.s[5] = {Ss_h + SS, Ss_l + SS, chsT_h + SE, chsT_l + SE, Ta3 + SE, nullptr, 1.f};
    gemmN(t, 6, S_DIM, E_DIM, S_DIM);
    {
        dim3 g3(E_DIM / 32, S_DIM / 32, B_DIM), b3(32, 8);
        splitT3_kernel<<<g3, b3>>>(Ta1, Ta2, Ta3, orT_h, orT_l, oiT_h, oiT_l);
    }
    /* IDFT: z=4 — P1 = (1/S) cos@orT ; P2 = -(1/S) sin@oiT */
    t = GTable{};
    t.s[0] = {cos_h, cos_l, orT_h,      orT_l,      P1,      nullptr, invS};
    t.s[1] = {cos_h, cos_l, orT_h + SE, orT_l + SE, P1 + SE, nullptr, invS};
    t.s[2] = {sin_h, sin_l, oiT_h,      oiT_l,      P2,      nullptr, -invS};
    t.s[3] = {sin_h, sin_l, oiT_h + SE, oiT_l + SE, P2 + SE, nullptr, -invS};
    gemmN(t, 4, S_DIM, E_DIM, S_DIM);

    /* ============ Wavelet ============ */
    split(Wp_w, w_h, w_l, (size_t)E_DIM * E_DIM);
    gemm1(q_h, q_l, w_h, w_l, bp_w, xd, BS_DIM, E_DIM, E_DIM);
    {
        const float* cur = xd;
        float* nx = haar0;
        for (int L = S_DIM; L >= 2; L >>= 1) {
            size_t tot = (size_t)B_DIM * (L >> 1) * E_DIM;
            haar_level_kernel<<<(unsigned)((tot + 255) / 256), 256>>>(cur, nx, sr, L);
            cur = nx;
            nx = (nx == haar0) ? haar1 : haar0;
        }
    }
    conv1d_kernel<<<BS_DIM, 512>>>(sr, Wc_w, bc_w, chtr);
    fweights_kernel<<<4, 256>>>(Fw, fwbuf);
    mix_real_kernel<<<NB_MIX, 256>>>(chtr, fwbuf, chr, chr_h, chr_l);
    splitT(chr, chrT_h, chrT_l, S_DIM, E_DIM, B_DIM);
    t = GTable{};
    t.s[0] = {chr_h,      chr_l,      chr_h,      chr_l,      Ts1,      nullptr, 1.f};
    t.s[1] = {chr_h + SE, chr_l + SE, chr_h + SE, chr_l + SE, Ts1 + SS, nullptr, 1.f};
    gemmN(t, 2, S_DIM, S_DIM, E_DIM);
    softmax_real_bf16<<<2 * S_DIM, 256>>>(Ts1, Sr_h, Sr_l, inv_sqE);
    t = GTable{};
    t.s[0] = {Sr_h,      Sr_l,      chrT_h,      chrT_l,      outw,      nullptr, 1.f};
    t.s[1] = {Sr_h + SS, Sr_l + SS, chrT_h + SE, chrT_l + SE, outw + SE, nullptr, 1.f};
    gemmN(t, 2, S_DIM, E_DIM, S_DIM);

    /* ============ Cosine (DCT) ============ */
    split(Wp_c, w_h, w_l, (size_t)E_DIM * E_DIM);
    gemm1(q_h, q_l, w_h, w_l, bp_c, xd, BS_DIM, E_DIM, E_DIM);
    splitT(xd, xdT_h, xdT_l, S_DIM, E_DIM, B_DIM);
    t = GTable{};
    t.s[0] = {dctD_h, dctD_l, xdT_h,      xdT_l,      sr,      nullptr, 1.f};
    t.s[1] = {dctD_h, dctD_l, xdT_h + SE, xdT_l + SE, sr + SE, nullptr, 1.f};
    gemmN(t, 2, S_DIM, E_DIM, S_DIM);
    conv1d_kernel<<<BS_DIM, 512>>>(sr, Wc_c, bc_c, chtr);
    fweights_kernel<<<4, 256>>>(Fc, fwbuf);
    mix_real_kernel<<<NB_MIX, 256>>>(chtr, fwbuf, chr, chr_h, chr_l);
    splitT(chr, chrT_h, chrT_l, S_DIM, E_DIM, B_DIM);
    t = GTable{};
    t.s[0] = {chr_h,      chr_l,      chr_h,      chr_l,      Ts1,      nullptr, 1.f};
    t.s[1] = {chr_h + SE, chr_l + SE, chr_h + SE, chr_l + SE, Ts1 + SS, nullptr, 1.f};
    gemmN(t, 2, S_DIM, S_DIM, E_DIM);
    softmax_real_bf16<<<2 * S_DIM, 256>>>(Ts1, Sr_h, Sr_l, inv_sqE);
    t = GTable{};
    t.s[0] = {Sr_h,      Sr_l,      chrT_h,      chrT_l,      Ta1,      nullptr, 1.f};
    t.s[1] = {Sr_h + SS, Sr_l + SS, chrT_h + SE, chrT_l + SE, Ta1 + SE, nullptr, 1.f};
    gemmN(t, 2, S_DIM, E_DIM, S_DIM);
    splitT(Ta1, orT_h, orT_l, S_DIM, E_DIM, B_DIM);
    t = GTable{};
    t.s[0] = {dctI_h, dctI_l, orT_h,      orT_l,      outc,      nullptr, 1.f};
    t.s[1] = {dctI_h, dctI_l, orT_h + SE, orT_l + SE, outc + SE, nullptr, 1.f};
    gemmN(t, 2, S_DIM, E_DIM, S_DIM);

    /* ============ cross-domain MHA + fusion ============ */
    stack3_bf16<<<(unsigned)((3 * BSE + 255) / 256), 256>>>(P1, P2, outw, outc, xstk_h, xstk_l);
    split(mha_iw, w_h, w_l, (size_t)3 * E_DIM * E_DIM);
    gemm1(xstk_h, xstk_l, w_h, w_l, mha_ib, qkv, T3_DIM, 3 * E_DIM, E_DIM);
    mha_small_attn<<<(BS_DIM * 16 * 32) / 256, 256>>>(qkv, att);
    split(att, att_h, att_l, 3 * BSE);
    split(mha_ow, w_h, w_l, (size_t)E_DIM * E_DIM);
    gemm1(att_h, att_l, w_h, w_l, mha_ob, corr, T3_DIM, E_DIM, E_DIM);
    split(corr, corr_h, corr_l, 3 * BSE);
    split(fus_W, w_h, w_l, (size_t)3 * E_DIM * E_DIM);
    gemm1(corr_h, corr_l, w_h, w_l, fus_b, out, BS_DIM, E_DIM, 3 * E_DIM);
}

// round 16
// speedup vs baseline: 2.9704x; 1.0588x over previous
#include <cuda_runtime.h>
#include <cuda_bf16.h>
#include <math.h>
#include <stdint.h>

#define B_DIM 2
#define S_DIM 2048
#define E_DIM 1024
#define C_DIM 16
#define BS_DIM (B_DIM * S_DIM)          /* 4096  */
#define T3_DIM (BS_DIM * 3)             /* 12288 */
#define EE ((size_t)E_DIM * E_DIM)

typedef __nv_bfloat16 bf;

static const size_t BSE = (size_t)BS_DIM * E_DIM;     /* 4194304 */
static const size_t SE  = (size_t)S_DIM * E_DIM;      /* 2097152 */
static const size_t SS  = (size_t)S_DIM * S_DIM;      /* 4194304 */
#define BF_UNIT 4194304ULL

/* fp32 scratch: 32 units (~537 MB) */
__device__ float g_arena[32ULL * BF_UNIT];
/* bf16 scratch: 56 units (~470 MB) */
__device__ bf g_bfarena[56ULL * BF_UNIT];

__device__ __forceinline__ uint32_t smem_to_u32(const void* p) {
    uint32_t a;
    asm("{ .reg .u64 t; cvta.to.shared.u64 t, %1; cvt.u32.u64 %0, t; }"
        : "=r"(a) : "l"(p));
    return a;
}

/* ================= warp-MMA primitives (compute_103-safe) ============== */
__device__ __forceinline__ void ldmx4(uint32_t* r, uint32_t a) {
    asm volatile("ldmatrix.sync.aligned.m8n8.x4.shared.b16 {%0,%1,%2,%3}, [%4];"
                 : "=r"(r[0]), "=r"(r[1]), "=r"(r[2]), "=r"(r[3]) : "r"(a));
}
__device__ __forceinline__ void mma16816(float* c, const uint32_t* a, const uint32_t* b) {
    asm volatile(
        "mma.sync.aligned.m16n8k16.row.col.f32.bf16.bf16.f32 "
        "{%0,%1,%2,%3}, {%4,%5,%6,%7}, {%8,%9}, {%0,%1,%2,%3};"
        : "+f"(c[0]), "+f"(c[1]), "+f"(c[2]), "+f"(c[3])
        : "r"(a[0]), "r"(a[1]), "r"(a[2]), "r"(a[3]), "r"(b[0]), "r"(b[1]));
}
__device__ __forceinline__ void cpa16(uint32_t d, const void* s) {
    asm volatile("cp.async.cg.shared.global [%0], [%1], 16;" :: "r"(d), "l"(s));
}
#define CP_COMMIT() asm volatile("cp.async.commit_group;" ::: "memory")
#define CP_WAIT0()  asm volatile("cp.async.wait_group 0;" ::: "memory")
#define CP_WAIT1()  asm volatile("cp.async.wait_group 1;" ::: "memory")

/* ================= reductions ========================================== */
__device__ __forceinline__ float warpReduceSum(float v) {
#pragma unroll
    for (int o = 16; o; o >>= 1) v += __shfl_xor_sync(0xffffffffu, v, o);
    return v;
}
__device__ __forceinline__ float warpReduceMax(float v) {
#pragma unroll
    for (int o = 16; o; o >>= 1) v = fmaxf(v, __shfl_xor_sync(0xffffffffu, v, o));
    return v;
}
__device__ float blockReduceSum(float v) {
    __shared__ float sh[32];
    __syncthreads();
    int lane = threadIdx.x & 31, wid = threadIdx.x >> 5;
    v = warpReduceSum(v);
    if (lane == 0) sh[wid] = v;
    __syncthreads();
    float r = (threadIdx.x < (blockDim.x >> 5)) ? sh[threadIdx.x] : 0.f;
    r = warpReduceSum(r);
    if (threadIdx.x == 0) sh[0] = r;
    __syncthreads();
    return sh[0];
}
__device__ float blockReduceMax(float v) {
    __shared__ float sh[32];
    __syncthreads();
    int lane = threadIdx.x & 31, wid = threadIdx.x >> 5;
    v = warpReduceMax(v);
    if (lane == 0) sh[wid] = v;
    __syncthreads();
    float r = (threadIdx.x < (blockDim.x >> 5)) ? sh[threadIdx.x] : -3.4e38f;
    r = warpReduceMax(r);
    if (threadIdx.x == 0) sh[0] = r;
    __syncthreads();
    return sh[0];
}

/* ================= unified slice-table split-fp32 GEMM ================= */
/* Per z-slice: C(M,N) = alpha * A(M,K) @ B(N,K)^T + bias[col].           */
struct GSlice {
    const bf* Ah; const bf* Al; const bf* Bh; const bf* Bl;
    float* C; const float* bias; float alpha;
};
struct GTable { GSlice s[6]; };

/* BK=32; PITCH = 64B data + 16B pad -> conflict-free LDSM, 2 CTAs/SM */
#define PITCH 80
#define TILE_B (128 * PITCH)             /* 10240 */
#define STAGE_B (4 * TILE_B)             /* 40960 */
#define GEMM_SMEM (2 * STAGE_B)          /* 81920 */

__global__ void __launch_bounds__(256, 2) gemm_tc(
    GTable tab, int M, int N, int K)
{
    extern __shared__ char smem[];
    const uint32_t su = smem_to_u32(smem);
    const int tid = threadIdx.x;
    const int lane = tid & 31, wid = tid >> 5;
    const int wm = (wid >> 2) * 64;
    const int wn = (wid & 3) * 32;

    const GSlice sl = tab.s[blockIdx.z];
    float* Cb = sl.C;
    const int bm = blockIdx.y * 128;
    const int bn = blockIdx.x * 128;
    const float alpha = sl.alpha;

    const bf* srcs[4];
    srcs[0] = sl.Ah + (size_t)bm * K;
    srcs[1] = sl.Al + (size_t)bm * K;
    srcs[2] = sl.Bh + (size_t)bn * K;
    srcs[3] = sl.Bl + (size_t)bn * K;

    float c[4][4][4];
#pragma unroll
    for (int i = 0; i < 4; i++)
#pragma unroll
        for (int j = 0; j < 4; j++)
#pragma unroll
            for (int k = 0; k < 4; k++) c[i][j][k] = 0.f;

    const int nch = K / 32;

#define LOADSTAGE(s, k0) do {                                              \
        uint32_t sb_ = su + (s) * STAGE_B;                                 \
        _Pragma("unroll")                                                  \
        for (int t_ = 0; t_ < 4; t_++) {                                   \
            _Pragma("unroll")                                              \
            for (int j_ = 0; j_ < 2; j_++) {                               \
                int idx_ = j_ * 256 + tid;                                 \
                int row_ = idx_ >> 2;                                      \
                int cc_ = idx_ & 3;                                        \
                uint32_t d_ = sb_ + t_ * TILE_B + row_ * PITCH + cc_ * 16; \
                const void* g_ = srcs[t_] + (size_t)row_ * K + (k0) + cc_ * 8; \
                cpa16(d_, g_);                                             \
            }                                                              \
        }                                                                  \
        CP_COMMIT();                                                       \
    } while (0)

    LOADSTAGE(0, 0);

    const int qa = lane >> 3;
    const int ra = lane & 7;
    const int arow = (qa & 1) * 8 + ra;
    const int acol = (qa >> 1) * 16;
    const int bsub  = lane >> 4;
    const int bhalf = (lane >> 3) & 1;
    const int brow2 = lane & 7;

    for (int i = 0; i < nch; i++) {
        if (i + 1 < nch) { LOADSTAGE((i + 1) & 1, (i + 1) * 32); CP_WAIT1(); }
        else             { CP_WAIT0(); }
        __syncthreads();

        const uint32_t sb = su + (i & 1) * STAGE_B;
#pragma unroll
        for (int kk = 0; kk < 2; kk++) {
            uint32_t fAh[4][4], fAl[4][4], fBh[4][2], fBl[4][2];
#pragma unroll
            for (int mt = 0; mt < 4; mt++) {
                uint32_t a = sb + (wm + mt * 16 + arow) * PITCH + kk * 32 + acol;
                ldmx4(fAh[mt], a);
                ldmx4(fAl[mt], a + TILE_B);
            }
#pragma unroll
            for (int ntp = 0; ntp < 2; ntp++) {
                uint32_t a = sb + 2 * TILE_B +
                             (wn + (ntp * 2 + bsub) * 8 + brow2) * PITCH + kk * 32 + bhalf * 16;
                uint32_t t[4];
                ldmx4(t, a);
                fBh[ntp * 2][0] = t[0]; fBh[ntp * 2][1] = t[1];
                fBh[ntp * 2 + 1][0] = t[2]; fBh[ntp * 2 + 1][1] = t[3];
                ldmx4(t, a + TILE_B);
                fBl[ntp * 2][0] = t[0]; fBl[ntp * 2][1] = t[1];
                fBl[ntp * 2 + 1][0] = t[2]; fBl[ntp * 2 + 1][1] = t[3];
            }
#pragma unroll
            for (int mt = 0; mt < 4; mt++)
#pragma unroll
                for (int nt = 0; nt < 4; nt++) {
                    mma16816(c[mt][nt], fAh[mt], fBh[nt]);
                    mma16816(c[mt][nt], fAh[mt], fBl[nt]);
                    mma16816(c[mt][nt], fAl[mt], fBh[nt]);
                }
        }
        __syncthreads();
    }

    const int g = lane >> 2, t4 = lane & 3;
#pragma unroll
    for (int mt = 0; mt < 4; mt++) {
#pragma unroll
        for (int nt = 0; nt < 4; nt++) {
            const int col = bn + wn + nt * 8 + 2 * t4;
            const int row0 = bm + wm + mt * 16 + g;
            float bv0 = 0.f, bv1 = 0.f;
            if (sl.bias) { bv0 = sl.bias[col]; bv1 = sl.bias[col + 1]; }
            float2 v0, v1;
            v0.x = alpha * c[mt][nt][0] + bv0;
            v0.y = alpha * c[mt][nt][1] + bv1;
            v1.x = alpha * c[mt][nt][2] + bv0;
            v1.y = alpha * c[mt][nt][3] + bv1;
            *reinterpret_cast<float2*>(&Cb[(size_t)row0 * N + col]) = v0;
            *reinterpret_cast<float2*>(&Cb[(size_t)(row0 + 8) * N + col]) = v1;
        }
    }
}

static void gemm1(const bf* Ah, const bf* Al, const bf* Bh, const bf* Bl,
                  const float* bias, float* C, int M, int N, int K)
{
    GTable t{};
    t.s[0] = {Ah, Al, Bh, Bl, C, bias, 1.f};
    dim3 grid(N / 128, M / 128, 1), block(256);
    gemm_tc<<<grid, block, GEMM_SMEM>>>(t, M, N, K);
}
static void gemmN(const GTable& t, int nz, int M, int N, int K)
{
    dim3 grid(N / 128, M / 128, nz), block(256);
    gemm_tc<<<grid, block, GEMM_SMEM>>>(t, M, N, K);
}

/* ================= fp32 -> bf16 hi/lo conversions ====================== */
__device__ __forceinline__ void split2(float x, bf& h, bf& l) {
    h = __float2bfloat16(x);
    l = __float2bfloat16(x - __bfloat162float(h));
}

__global__ void split_kernel(const float* __restrict__ in, bf* __restrict__ oh,
                             bf* __restrict__ ol, size_t n4)
{
    size_t i = (size_t)blockIdx.x * blockDim.x + threadIdx.x;
    if (i >= n4) return;
    float4 v = reinterpret_cast<const float4*>(in)[i];
    bf h[4], l[4];
    split2(v.x, h[0], l[0]); split2(v.y, h[1], l[1]);
    split2(v.z, h[2], l[2]); split2(v.w, h[3], l[3]);
    reinterpret_cast<ulonglong1*>(oh)[i] = *reinterpret_cast<ulonglong1*>(h);
    reinterpret_cast<ulonglong1*>(ol)[i] = *reinterpret_cast<ulonglong1*>(l);
}
static void split(const float* in, bf* oh, bf* ol, size_t n)
{
    size_t n4 = n / 4;
    split_kernel<<<(unsigned)((n4 + 255) / 256), 256>>>(in, oh, ol, n4);
}

/* per-batch transpose (R,C)->(C,R) with split */
__global__ void splitT_kernel(const float* __restrict__ in, bf* __restrict__ oh,
                              bf* __restrict__ ol, int R, int Cc)
{
    __shared__ float t[32][33];
    const int b = blockIdx.z;
    const float* ib = in + (size_t)b * R * Cc;
    bf* ohb = oh + (size_t)b * R * Cc;
    bf* olb = ol + (size_t)b * R * Cc;
    const int c0 = blockIdx.x * 32, r0 = blockIdx.y * 32;
#pragma unroll
    for (int k = 0; k < 4; k++)
        t[threadIdx.y + k * 8][threadIdx.x] =
            ib[(size_t)(r0 + threadIdx.y + k * 8) * Cc + c0 + threadIdx.x];
    __syncthreads();
#pragma unroll
    for (int k = 0; k < 4; k++) {
        float v = t[threadIdx.x][threadIdx.y + k * 8];
        bf h, l;
        split2(v, h, l);
        size_t o = (size_t)(c0 + threadIdx.y + k * 8) * R + r0 + threadIdx.x;
        ohb[o] = h;
        olb[o] = l;
    }
}
static void splitT(const float* in, bf* oh, bf* ol, int R, int Cc, int batch)
{
    dim3 grid(Cc / 32, R / 32, batch), block(32, 8);
    splitT_kernel<<<grid, block>>>(in, oh, ol, R, Cc);
}

/* 3M attnout combine + transpose + split: Or=T1-T2, Oi=T3-T1-T2 */
__global__ void splitT3_kernel(const float* __restrict__ T1, const float* __restrict__ T2,
                               const float* __restrict__ T3,
                               bf* __restrict__ orh, bf* __restrict__ orl,
                               bf* __restrict__ oih, bf* __restrict__ oil)
{
    __shared__ float tr[32][33], ti[32][33];
    const int b = blockIdx.z;
    const size_t base = (size_t)b * SE;
    const int c0 = blockIdx.x * 32, r0 = blockIdx.y * 32;
#pragma unroll
    for (int k = 0; k < 4; k++) {
        size_t idx = base + (size_t)(r0 + threadIdx.y + k * 8) * E_DIM + c0 + threadIdx.x;
        float a = T1[idx], bb = T2[idx], cc = T3[idx];
        tr[threadIdx.y + k * 8][threadIdx.x] = a - bb;
        ti[threadIdx.y + k * 8][threadIdx.x] = cc - a - bb;
    }
    __syncthreads();
#pragma unroll
    for (int k = 0; k < 4; k++) {
        size_t o = base + (size_t)(c0 + threadIdx.y + k * 8) * S_DIM + r0 + threadIdx.x;
        bf h, l;
        split2(tr[threadIdx.x][threadIdx.y + k * 8], h, l);
        orh[o] = h; orl[o] = l;
        split2(ti[threadIdx.x][threadIdx.y + k * 8], h, l);
        oih[o] = h; oil[o] = l;
    }
}

/* ================= basis fills (bf16 hi/lo direct) ===================== */
__global__ void fill_dft_bf16(bf* __restrict__ ch, bf* __restrict__ cl,
                              bf* __restrict__ sh_, bf* __restrict__ sl)
{
    size_t i = (size_t)blockIdx.x * blockDim.x + threadIdx.x;
    if (i >= (size_t)S_DIM * S_DIM) return;
    int s = (int)(i / S_DIM), t = (int)(i % S_DIM);
    int p = (int)(((long long)s * (long long)t) & (S_DIM - 1));
    float sv, cv;
    sincospif((float)p / 1024.0f, &sv, &cv);
    bf h, l;
    split2(cv, h, l); ch[i] = h; cl[i] = l;
    split2(sv, h, l); sh_[i] = h; sl[i] = l;
}

__global__ void fill_dct_bf16(bf* __restrict__ dh, bf* __restrict__ dl,
                              bf* __restrict__ ih, bf* __restrict__ il)
{
    size_t idx = (size_t)blockIdx.x * blockDim.x + threadIdx.x;
    if (idx >= (size_t)S_DIM * S_DIM) return;
    int i = (int)(idx / S_DIM), j = (int)(idx % S_DIM);
    const float PI_F = (float)M_PI;
    const float s0 = 0.02209708691207961f;
    const float s1 = 0.03125f;
    bf h, l;
    float a  = PI_F * (float)i;
    float b  = a * (float)(2 * j + 1);
    float vD = cosf(b / (float)(2 * S_DIM)) * (i == 0 ? s0 : s1);
    split2(vD, h, l); dh[idx] = h; dl[idx] = l;
    float a2 = PI_F * (float)j;
    float b2 = a2 * (float)(2 * i + 1);
    float vI = cosf(b2 / (float)(2 * S_DIM)) * (j == 0 ? s0 : s1);
    split2(vI, h, l); ih[idx] = h; il[idx] = l;
}

/* ================= conv / mix / softmax / haar ========================= */
__global__ void __launch_bounds__(512) conv1d_kernel(
    const float* __restrict__ x, const float* __restrict__ Wc,
    const float* __restrict__ bc, float* __restrict__ out)
{
    __shared__ float xs[3 * E_DIM];
    int bs = blockIdx.x;
    int b = bs >> 11;
    int s = bs & 2047;
    for (int i = threadIdx.x; i < 3 * E_DIM; i += 512) {
        int tap = i >> 10;
        int e = i & 1023;
        int sp = s + tap - 1;
        xs[i] = (sp >= 0 && sp < S_DIM) ? x[((size_t)b * S_DIM + sp) * E_DIM + e] : 0.f;
    }
    __syncthreads();
    int c = threadIdx.x >> 5, lane = threadIdx.x & 31;
    const float* w = Wc + (size_t)c * E_DIM * 3;
    float acc = 0.f;
    for (int e = lane; e < E_DIM; e += 32) {
        float x0 = xs[e], x1 = xs[E_DIM + e], x2 = xs[2 * E_DIM + e];
        acc += w[e * 3 + 0] * x0 + w[e * 3 + 1] * x1 + w[e * 3 + 2] * x2;
    }
    acc = warpReduceSum(acc);
    if (lane == 0) out[(size_t)bs * C_DIM + c] = acc + bc[c];
}

/* real+imag fused conv: weight rows read once */
__global__ void __launch_bounds__(512) conv1d_c_kernel(
    const float* __restrict__ xr, const float* __restrict__ xi,
    const float* __restrict__ Wc, const float* __restrict__ bc,
    float* __restrict__ outr, float* __restrict__ outi)
{
    __shared__ float xsr[3 * E_DIM];
    __shared__ float xsi[3 * E_DIM];
    int bs = blockIdx.x;
    int b = bs >> 11;
    int s = bs & 2047;
    for (int i = threadIdx.x; i < 3 * E_DIM; i += 512) {
        int tap = i >> 10;
        int e = i & 1023;
        int sp = s + tap - 1;
        bool in = (sp >= 0 && sp < S_DIM);
        size_t gi = ((size_t)b * S_DIM + sp) * E_DIM + e;
        xsr[i] = in ? xr[gi] : 0.f;
        xsi[i] = in ? xi[gi] : 0.f;
    }
    __syncthreads();
    int c = threadIdx.x >> 5, lane = threadIdx.x & 31;
    const float* w = Wc + (size_t)c * E_DIM * 3;
    float ar = 0.f, ai = 0.f;
    for (int e = lane; e < E_DIM; e += 32) {
        float w0 = w[e * 3 + 0], w1 = w[e * 3 + 1], w2 = w[e * 3 + 2];
        ar += w0 * xsr[e] + w1 * xsr[E_DIM + e] + w2 * xsr[2 * E_DIM + e];
        ai += w0 * xsi[e] + w1 * xsi[E_DIM + e] + w2 * xsi[2 * E_DIM + e];
    }
    ar = warpReduceSum(ar);
    ai = warpReduceSum(ai);
    if (lane == 0) {
        outr[(size_t)bs * C_DIM + c] = ar + bc[c];
        outi[(size_t)bs * C_DIM + c] = ai + bc[c];
    }
}

__global__ void fweights_kernel(const float* __restrict__ F, float* __restrict__ fw)
{
    int e = blockIdx.x * blockDim.x + threadIdx.x;
    if (e >= E_DIM) return;
    float v[C_DIM], m = -3.4e38f;
#pragma unroll
    for (int c = 0; c < C_DIM; c++) { v[c] = F[c * E_DIM + e]; m = fmaxf(m, v[c]); }
    float s = 0.f;
#pragma unroll
    for (int c = 0; c < C_DIM; c++) { v[c] = expf(v[c] - m); s += v[c]; }
    float inv = 1.f / s;
#pragma unroll
    for (int c = 0; c < C_DIM; c++) fw[c * E_DIM + e] = v[c] * inv;
}

/* mix real: fp32 + fused split */
__global__ void mix_real_kernel(const float* __restrict__ ch, const float* __restrict__ fw,
                                float* __restrict__ out, bf* __restrict__ oh, bf* __restrict__ ol)
{
    size_t i = (size_t)blockIdx.x * blockDim.x + threadIdx.x;
    if (i >= (size_t)BS_DIM * E_DIM) return;
    int e = (int)(i & 1023);
    size_t bs = i >> 10;
    const float* cr = ch + bs * C_DIM;
    float a = 0.f;
#pragma unroll
    for (int c = 0; c < C_DIM; c++) a += cr[c] * fw[c * E_DIM + e];
    out[i] = a;
    bf h, l;
    split2(a, h, l);
    oh[i] = h; ol[i] = l;
}

/* mix complex: r, i, s=r+i (fp32 for transposes) + fused splits */
__global__ void mix_complex_kernel(
    const float* __restrict__ chr_, const float* __restrict__ chi_,
    const float* __restrict__ fw,
    float* __restrict__ outr, float* __restrict__ outi, float* __restrict__ outs,
    bf* __restrict__ rh, bf* __restrict__ rl, bf* __restrict__ ih2, bf* __restrict__ il2,
    bf* __restrict__ sh2, bf* __restrict__ sl2)
{
    size_t i = (size_t)blockIdx.x * blockDim.x + threadIdx.x;
    if (i >= (size_t)BS_DIM * E_DIM) return;
    int e = (int)(i & 1023);
    size_t bs = i >> 10;
    const float* cr = chr_ + bs * C_DIM;
    const float* ci = chi_ + bs * C_DIM;
    float ar = 0.f, ai = 0.f;
#pragma unroll
    for (int c = 0; c < C_DIM; c++) {
        float w = fw[c * E_DIM + e];
        ar += cr[c] * w;
        ai += ci[c] * w;
    }
    float as = ar + ai;
    outr[i] = ar; outi[i] = ai; outs[i] = as;
    bf h, l;
    split2(ar, h, l); rh[i] = h; rl[i] = l;
    split2(ai, h, l); ih2[i] = h; il2[i] = l;
    split2(as, h, l); sh2[i] = h; sl2[i] = l;
}

/* real softmax: fp32 scores in, bf16 hi/lo weights out (row = 2048) */
__global__ void __launch_bounds__(256) softmax_real_bf16(
    const float* __restrict__ T, bf* __restrict__ oh, bf* __restrict__ ol, float scale)
{
    size_t base = (size_t)blockIdx.x * S_DIM;
    int tid = threadIdx.x;
    float v[8];
    float m = -3.4e38f;
#pragma unroll
    for (int j = 0; j < 8; j++) {
        v[j] = T[base + tid + j * 256];
        m = fmaxf(m, v[j]);
    }
    m = blockReduceMax(m);
    float s = 0.f;
#pragma unroll
    for (int j = 0; j < 8; j++) {
        v[j] = expf((v[j] - m) * scale);
        s += v[j];
    }
    s = blockReduceSum(s);
    float inv = 1.f / s;
#pragma unroll
    for (int j = 0; j < 8; j++) {
        bf h, l;
        split2(v[j] * inv, h, l);
        oh[base + tid + j * 256] = h;
        ol[base + tid + j * 256] = l;
    }
}

/* complex softmax with 3M combine */
__global__ void __launch_bounds__(256) softmax_c3m(
    const float* __restrict__ T1, const float* __restrict__ T2, const float* __restrict__ T3,
    bf* __restrict__ rh, bf* __restrict__ rl, bf* __restrict__ ih2, bf* __restrict__ il2,
    bf* __restrict__ sh2, bf* __restrict__ sl2, float scale)
{
    size_t base = (size_t)blockIdx.x * S_DIM;
    int tid = threadIdx.x;
    float sr[8], si[8];
    float m = -3.4e38f;
#pragma unroll
    for (int j = 0; j < 8; j++) {
        size_t idx = base + tid + j * 256;
        float a = T1[idx], b = T2[idx], c = T3[idx];
        sr[j] = a - b;
        si[j] = c - a - b;
        m = fmaxf(m, sr[j]);
    }
    m = blockReduceMax(m);
    float s = 0.f;
#pragma unroll
    for (int j = 0; j < 8; j++) {
        float p = expf((sr[j] - m) * scale);
        s += p;
        float mag = sqrtf(sr[j] * sr[j] + si[j] * si[j]);
        float ur, ui;
        if (mag > 0.f) { ur = sr[j] / mag; ui = si[j] / mag; }
        else           { ur = 1.f;         ui = 0.f;         }
        sr[j] = p * ur;
        si[j] = p * ui;
    }
    s = blockReduceSum(s);
    float inv = 1.f / s;
#pragma unroll
    for (int j = 0; j < 8; j++) {
        size_t idx = base + tid + j * 256;
        float r = sr[j] * inv, i2 = si[j] * inv;
        bf h, l;
        split2(r, h, l);      rh[idx] = h;  rl[idx] = l;
        split2(i2, h, l);     ih2[idx] = h; il2[idx] = l;
        split2(r + i2, h, l); sh2[idx] = h; sl2[idx] = l;
    }
}

__global__ void haar_level_kernel(const float* __restrict__ cur, float* __restrict__ nxt,
                                  float* __restrict__ sbuf, int L)
{
    int half = L >> 1;
    size_t total = (size_t)B_DIM * half * E_DIM;
    size_t i = (size_t)blockIdx.x * blockDim.x + threadIdx.x;
    if (i >= total) return;
    int e = (int)(i % E_DIM);
    size_t t = i / E_DIM;
    int j = (int)(t % half);
    int b = (int)(t / half);
    const float SQ2F = 1.41421356237309515f;
    float ev = cur[((size_t)b * L + 2 * j) * E_DIM + e];
    float ov = cur[((size_t)b * L + 2 * j + 1) * E_DIM + e];
    sbuf[((size_t)b * S_DIM + half + j) * E_DIM + e] = (ev - ov) / SQ2F;
    float ap = (ev + ov) / SQ2F;
    nxt[((size_t)b * half + j) * E_DIM + e] = ap;
    if (half == 1) sbuf[((size_t)b * S_DIM) * E_DIM + e] = ap;
}

/* stack: f = P1+P2 (pre-scaled IDFT partials), w = outw, c = outc */
__global__ void stack3_bf16(const float* __restrict__ P1, const float* __restrict__ P2,
                            const float* __restrict__ w, const float* __restrict__ c,
                            bf* __restrict__ xh, bf* __restrict__ xl)
{
    size_t i = (size_t)blockIdx.x * blockDim.x + threadIdx.x;
    if (i >= 3 * (size_t)BS_DIM * E_DIM) return;
    size_t e = i % E_DIM;
    size_t t = i / E_DIM;
    size_t d = t % 3, bs = t / 3;
    size_t src = bs * E_DIM + e;
    float v;
    if (d == 0)      v = P1[src] + P2[src];
    else if (d == 1) v = w[src];
    else             v = c[src];
    bf h, l;
    split2(v, h, l);
    xh[i] = h;
    xl[i] = l;
}

__global__ void mha_small_attn(const float* __restrict__ qkv, float* __restrict__ out)
{
    int gw = (int)(((size_t)blockIdx.x * blockDim.x + threadIdx.x) >> 5);
    int lane = threadIdx.x & 31;
    if (gw >= BS_DIM * 16) return;
    int g = gw >> 4, h = gw & 15;
    const float* base = qkv + (size_t)g * 3 * 3072 + h * 64;
    float q[3][2], k[3][2], v[3][2];
#pragma unroll
    for (int l = 0; l < 3; l++) {
        q[l][0] = base[(size_t)l * 3072 + lane];
        q[l][1] = base[(size_t)l * 3072 + lane + 32];
        k[l][0] = base[(size_t)l * 3072 + 1024 + lane];
        k[l][1] = base[(size_t)l * 3072 + 1024 + lane + 32];
        v[l][0] = base[(size_t)l * 3072 + 2048 + lane];
        v[l][1] = base[(size_t)l * 3072 + 2048 + lane + 32];
    }
    float sc[3][3];
#pragma unroll
    for (int l = 0; l < 3; l++)
#pragma unroll
        for (int m = 0; m < 3; m++) {
            float t = q[l][0] * k[m][0] + q[l][1] * k[m][1];
#pragma unroll
            for (int o = 16; o; o >>= 1) t += __shfl_xor_sync(0xffffffffu, t, o);
            sc[l][m] = t * 0.125f;
        }
    float a[3][3];
#pragma unroll
    for (int l = 0; l < 3; l++) {
        float m0 = fmaxf(sc[l][0], fmaxf(sc[l][1], sc[l][2]));
        float e0 = expf(sc[l][0] - m0);
        float e1 = expf(sc[l][1] - m0);
        float e2 = expf(sc[l][2] - m0);
        float s = e0 + e1 + e2;
        a[l][0] = e0 / s; a[l][1] = e1 / s; a[l][2] = e2 / s;
    }
    float* ob = out + (size_t)g * 3 * 1024 + h * 64;
#pragma unroll
    for (int l = 0; l < 3; l++) {
        float o0 = a[l][0] * v[0][0] + a[l][1] * v[1][0] + a[l][2] * v[2][0];
        float o1 = a[l][0] * v[0][1] + a[l][1] * v[1][1] + a[l][2] * v[2][1];
        ob[(size_t)l * 1024 + lane] = o0;
        ob[(size_t)l * 1024 + lane + 32] = o1;
    }
}

/* ================= orchestration ======================================= */
extern "C" void kernel_launch(void* const* d_in, const int* in_sizes, int n_in,
                              void* d_out, int out_size)
{
    (void)in_sizes; (void)n_in; (void)out_size;
    const float* query  = (const float*)d_in[0];
    const float* Wp_f   = (const float*)d_in[1];
    const float* bp_f   = (const float*)d_in[2];
    const float* Wc_f   = (const float*)d_in[3];
    const float* bc_f   = (const float*)d_in[4];
    const float* Ff     = (const float*)d_in[5];
    const float* Wp_w   = (const float*)d_in[6];
    const float* bp_w   = (const float*)d_in[7];
    const float* Wc_w   = (const float*)d_in[8];
    const float* bc_w   = (const float*)d_in[9];
    const float* Fw     = (const float*)d_in[10];
    const float* Wp_c   = (const float*)d_in[11];
    const float* bp_c   = (const float*)d_in[12];
    const float* Wc_c   = (const float*)d_in[13];
    const float* bc_c   = (const float*)d_in[14];
    const float* Fc     = (const float*)d_in[15];
    const float* mha_iw = (const float*)d_in[16];
    const float* mha_ib = (const float*)d_in[17];
    const float* mha_ow = (const float*)d_in[18];
    const float* mha_ob = (const float*)d_in[19];
    const float* fus_W  = (const float*)d_in[20];
    const float* fus_b  = (const float*)d_in[21];
    float* out = (float*)d_out;

    cudaFuncSetAttribute(gemm_tc, cudaFuncAttributeMaxDynamicSharedMemorySize, GEMM_SMEM);

    float* A = nullptr;
    bf* Z = nullptr;
    cudaGetSymbolAddress((void**)&A, g_arena);
    cudaGetSymbolAddress((void**)&Z, g_bfarena);

    /* fp32 units */
    float* xd_f  = A + 0 * BSE;
    float* xd_w  = A + 1 * BSE;
    float* xd_c  = A + 2 * BSE;
    float* sr    = A + 3 * BSE;
    float* si    = A + 4 * BSE;
    float* chr   = A + 5 * BSE;
    float* chi   = A + 6 * BSE;
    float* chs   = A + 7 * BSE;
    float* Ts1   = A + 8 * BSE;   /* 2 units */
    float* Ts2   = A + 10 * BSE;  /* 2 units */
    float* Ts3   = A + 12 * BSE;  /* 2 units */
    float* Ta1   = A + 14 * BSE;
    float* Ta2   = A + 15 * BSE;
    float* Ta3   = A + 16 * BSE;
    float* P1    = A + 17 * BSE;
    float* P2    = A + 18 * BSE;
    float* swav  = A + 19 * BSE;  /* wavelet haar spectrum */
    float* sc_   = A + 20 * BSE;  /* cosine DCT spectrum */
    float* ch_w  = A + 21 * BSE;
    float* ch_c  = A + 22 * BSE;
    float* Ts_wc = A + 23 * BSE;  /* 4 units: wav b0,b1, cos b0,b1 */
    float* outw  = A + 27 * BSE;
    float* Ta_c  = A + 28 * BSE;
    float* outc  = A + 29 * BSE;
    float* haar0 = A + 30 * BSE;
    float* haar1 = A + 30 * BSE + BSE / 2;
    float* chtr  = A + 31 * BSE;                 /* smalls inside unit 31 */
    float* chti  = A + 31 * BSE + 1 * 65536;
    float* chtw  = A + 31 * BSE + 2 * 65536;
    float* chtc  = A + 31 * BSE + 3 * 65536;
    float* fwbuf = A + 31 * BSE + 4 * 65536;
    float* fw_w  = A + 31 * BSE + 5 * 65536;
    float* fw_c  = A + 31 * BSE + 6 * 65536;
    /* MHA reuse (fourier fp32 free by then) */
    float* qkv   = A + 3 * BSE;   /* 9 units: 3..11 */
    float* att   = A + 12 * BSE;  /* 3 units: 12..14 */
    float* corr  = A + 15 * BSE;  /* 3 units: 15..17 */

    /* bf16 units */
    bf* cos_h  = Z + 0 * BF_UNIT;  bf* cos_l  = Z + 1 * BF_UNIT;
    bf* sin_h  = Z + 2 * BF_UNIT;  bf* sin_l  = Z + 3 * BF_UNIT;
    bf* dctD_h = Z + 4 * BF_UNIT;  bf* dctD_l = Z + 5 * BF_UNIT;
    bf* dctI_h = Z + 6 * BF_UNIT;  bf* dctI_l = Z + 7 * BF_UNIT;
    bf* q_h    = Z + 8 * BF_UNIT;  bf* q_l    = Z + 9 * BF_UNIT;
    bf* w_h    = Z + 10 * BF_UNIT; bf* w_l    = Z + 11 * BF_UNIT;  /* <=3M elems */
    bf* xdT_h  = Z + 12 * BF_UNIT; bf* xdT_l  = Z + 13 * BF_UNIT;
    bf* chr_h  = Z + 18 * BF_UNIT; bf* chr_l  = Z + 19 * BF_UNIT;
    bf* chi_h  = Z + 20 * BF_UNIT; bf* chi_l  = Z + 21 * BF_UNIT;
    bf* chs_h  = Z + 22 * BF_UNIT; bf* chs_l  = Z + 23 * BF_UNIT;
    bf* chrT_h = Z + 24 * BF_UNIT; bf* chrT_l = Z + 25 * BF_UNIT;
    bf* chiT_h = Z + 26 * BF_UNIT; bf* chiT_l = Z + 27 * BF_UNIT;
    bf* chsT_h = Z + 28 * BF_UNIT; bf* chsT_l = Z + 29 * BF_UNIT;
    bf* Sr_h   = Z + 30 * BF_UNIT; bf* Sr_l   = Z + 32 * BF_UNIT;  /* 2 units each */
    bf* Si_h   = Z + 34 * BF_UNIT; bf* Si_l   = Z + 36 * BF_UNIT;
    bf* Ss_h   = Z + 38 * BF_UNIT; bf* Ss_l   = Z + 40 * BF_UNIT;
    bf* orT_h  = Z + 42 * BF_UNIT; bf* orT_l  = Z + 43 * BF_UNIT;
    bf* oiT_h  = Z + 44 * BF_UNIT; bf* oiT_l  = Z + 45 * BF_UNIT;
    bf* xstk_h = Z + 46 * BF_UNIT; bf* xstk_l = Z + 49 * BF_UNIT;  /* 3 units each */
    /* wavelet+cosine reuse (fourier bf16 free after attnout z=6) */
    bf* chw_h  = Z + 18 * BF_UNIT; bf* chw_l  = Z + 19 * BF_UNIT;
    bf* chwT_h = Z + 20 * BF_UNIT; bf* chwT_l = Z + 21 * BF_UNIT;
    bf* chc_h  = Z + 22 * BF_UNIT; bf* chc_l  = Z + 23 * BF_UNIT;
    bf* chcT_h = Z + 24 * BF_UNIT; bf* chcT_l = Z + 25 * BF_UNIT;
    bf* Swc_h  = Z + 30 * BF_UNIT;                /* 4 units 30..33 */
    bf* Swc_l  = Z + 34 * BF_UNIT;                /* 4 units 34..37 */
    /* MHA reuse */
    bf* att_h  = Z + 30 * BF_UNIT; bf* att_l  = Z + 33 * BF_UNIT;  /* 3 each */
    bf* corr_h = Z + 36 * BF_UNIT; bf* corr_l = Z + 39 * BF_UNIT;

    const float inv_sqE = 1.f / 32.f;
    const float invS = 1.f / (float)S_DIM;
    const int NB_MIX = (int)((BSE + 255) / 256);

    fill_dft_bf16<<<(unsigned)((SS + 255) / 256), 256>>>(cos_h, cos_l, sin_h, sin_l);
    fill_dct_bf16<<<(unsigned)((SS + 255) / 256), 256>>>(dctD_h, dctD_l, dctI_h, dctI_l);
    split(query, q_h, q_l, BSE);
    split(Wp_f, w_h + 0 * EE, w_l + 0 * EE, EE);
    split(Wp_w, w_h + 1 * EE, w_l + 1 * EE, EE);
    split(Wp_c, w_h + 2 * EE, w_l + 2 * EE, EE);

    GTable t;

    /* all three projections: z=3 */
    t = GTable{};
    t.s[0] = {q_h, q_l, w_h + 0 * EE, w_l + 0 * EE, xd_f, bp_f, 1.f};
    t.s[1] = {q_h, q_l, w_h + 1 * EE, w_l + 1 * EE, xd_w, bp_w, 1.f};
    t.s[2] = {q_h, q_l, w_h + 2 * EE, w_l + 2 * EE, xd_c, bp_c, 1.f};
    gemmN(t, 3, BS_DIM, E_DIM, E_DIM);

    /* ============ Fourier ============ */
    splitT(xd_f, xdT_h, xdT_l, S_DIM, E_DIM, B_DIM);
    t = GTable{};
    t.s[0] = {cos_h, cos_l, xdT_h,      xdT_l,      sr,      nullptr, 1.f};
    t.s[1] = {cos_h, cos_l, xdT_h + SE, xdT_l + SE, sr + SE, nullptr, 1.f};
    t.s[2] = {sin_h, sin_l, xdT_h,      xdT_l,      si,      nullptr, -1.f};
    t.s[3] = {sin_h, sin_l, xdT_h + SE, xdT_l + SE, si + SE, nullptr, -1.f};
    gemmN(t, 4, S_DIM, E_DIM, S_DIM);
    conv1d_c_kernel<<<BS_DIM, 512>>>(sr, si, Wc_f, bc_f, chtr, chti);
    fweights_kernel<<<4, 256>>>(Ff, fwbuf);
    mix_complex_kernel<<<NB_MIX, 256>>>(chtr, chti, fwbuf, chr, chi, chs,
                                        chr_h, chr_l, chi_h, chi_l, chs_h, chs_l);
    splitT(chr, chrT_h, chrT_l, S_DIM, E_DIM, B_DIM);
    splitT(chi, chiT_h, chiT_l, S_DIM, E_DIM, B_DIM);
    splitT(chs, chsT_h, chsT_l, S_DIM, E_DIM, B_DIM);
    t = GTable{};
    t.s[0] = {chr_h,      chr_l,      chr_h,      chr_l,      Ts1,      nullptr, 1.f};
    t.s[1] = {chr_h + SE, chr_l + SE, chr_h + SE, chr_l + SE, Ts1 + SS, nullptr, 1.f};
    t.s[2] = {chi_h,      chi_l,      chi_h,      chi_l,      Ts2,      nullptr, 1.f};
    t.s[3] = {chi_h + SE, chi_l + SE, chi_h + SE, chi_l + SE, Ts2 + SS, nullptr, 1.f};
    t.s[4] = {chs_h,      chs_l,      chs_h,      chs_l,      Ts3,      nullptr, 1.f};
    t.s[5] = {chs_h + SE, chs_l + SE, chs_h + SE, chs_l + SE, Ts3 + SS, nullptr, 1.f};
    gemmN(t, 6, S_DIM, S_DIM, E_DIM);
    softmax_c3m<<<2 * S_DIM, 256>>>(Ts1, Ts2, Ts3, Sr_h, Sr_l, Si_h, Si_l, Ss_h, Ss_l, inv_sqE);
    t = GTable{};
    t.s[0] = {Sr_h,      Sr_l,      chrT_h,      chrT_l,      Ta1,      nullptr, 1.f};
    t.s[1] = {Sr_h + SS, Sr_l + SS, chrT_h + SE, chrT_l + SE, Ta1 + SE, nullptr, 1.f};
    t.s[2] = {Si_h,      Si_l,      chiT_h,      chiT_l,      Ta2,      nullptr, 1.f};
    t.s[3] = {Si_h + SS, Si_l + SS, chiT_h + SE, chiT_l + SE, Ta2 + SE, nullptr, 1.f};
    t.s[4] = {Ss_h,      Ss_l,      chsT_h,      chsT_l,      Ta3,      nullptr, 1.f};
    t.s[5] = {Ss_h + SS, Ss_l + SS, chsT_h + SE, chsT_l + SE, Ta3 + SE, nullptr, 1.f};
    gemmN(t, 6, S_DIM, E_DIM, S_DIM);
    {
        dim3 g3(E_DIM / 32, S_DIM / 32, B_DIM), b3(32, 8);
        splitT3_kernel<<<g3, b3>>>(Ta1, Ta2, Ta3, orT_h, orT_l, oiT_h, oiT_l);
    }
    t = GTable{};
    t.s[0] = {cos_h, cos_l, orT_h,      orT_l,      P1,      nullptr, invS};
    t.s[1] = {cos_h, cos_l, orT_h + SE, orT_l + SE, P1 + SE, nullptr, invS};
    t.s[2] = {sin_h, sin_l, oiT_h,      oiT_l,      P2,      nullptr, -invS};
    t.s[3] = {sin_h, sin_l, oiT_h + SE, oiT_l + SE, P2 + SE, nullptr, -invS};
    gemmN(t, 4, S_DIM, E_DIM, S_DIM);

    /* ============ Wavelet + Cosine (interleaved) ============ */
    {
        const float* cur = xd_w;
        float* nx = haar0;
        for (int L = S_DIM; L >= 2; L >>= 1) {
            size_t tot = (size_t)B_DIM * (L >> 1) * E_DIM;
            haar_level_kernel<<<(unsigned)((tot + 255) / 256), 256>>>(cur, nx, swav, L);
            cur = nx;
            nx = (nx == haar0) ? haar1 : haar0;
        }
    }
    splitT(xd_c, xdT_h, xdT_l, S_DIM, E_DIM, B_DIM);
    t = GTable{};
    t.s[0] = {dctD_h, dctD_l, xdT_h,      xdT_l,      sc_,      nullptr, 1.f};
    t.s[1] = {dctD_h, dctD_l, xdT_h + SE, xdT_l + SE, sc_ + SE, nullptr, 1.f};
    gemmN(t, 2, S_DIM, E_DIM, S_DIM);
    conv1d_kernel<<<BS_DIM, 512>>>(swav, Wc_w, bc_w, chtw);
    conv1d_kernel<<<BS_DIM, 512>>>(sc_, Wc_c, bc_c, chtc);
    fweights_kernel<<<4, 256>>>(Fw, fw_w);
    fweights_kernel<<<4, 256>>>(Fc, fw_c);
    mix_real_kernel<<<NB_MIX, 256>>>(chtw, fw_w, ch_w, chw_h, chw_l);
    mix_real_kernel<<<NB_MIX, 256>>>(chtc, fw_c, ch_c, chc_h, chc_l);
    splitT(ch_w, chwT_h, chwT_l, S_DIM, E_DIM, B_DIM);
    splitT(ch_c, chcT_h, chcT_l, S_DIM, E_DIM, B_DIM);
    /* scores z=4: wav b0,b1, cos b0,b1 -> Ts_wc contiguous */
    t = GTable{};
    t.s[0] = {chw_h,      chw_l,      chw_h,      chw_l,      Ts_wc + 0 * SS, nullptr, 1.f};
    t.s[1] = {chw_h + SE, chw_l + SE, chw_h + SE, chw_l + SE, Ts_wc + 1 * SS, nullptr, 1.f};
    t.s[2] = {chc_h,      chc_l,      chc_h,      chc_l,      Ts_wc + 2 * SS, nullptr, 1.f};
    t.s[3] = {chc_h + SE, chc_l + SE, chc_h + SE, chc_l + SE, Ts_wc + 3 * SS, nullptr, 1.f};
    gemmN(t, 4, S_DIM, S_DIM, E_DIM);
    softmax_real_bf16<<<4 * S_DIM, 256>>>(Ts_wc, Swc_h, Swc_l, inv_sqE);
    /* attn-out z=4 */
    t = GTable{};
    t.s[0] = {Swc_h + 0 * SS, Swc_l + 0 * SS, chwT_h,      chwT_l,      outw,      nullptr, 1.f};
    t.s[1] = {Swc_h + 1 * SS, Swc_l + 1 * SS, chwT_h + SE, chwT_l + SE, outw + SE, nullptr, 1.f};
    t.s[2] = {Swc_h + 2 * SS, Swc_l + 2 * SS, chcT_h,      chcT_l,      Ta_c,      nullptr, 1.f};
    t.s[3] = {Swc_h + 3 * SS, Swc_l + 3 * SS, chcT_h + SE, chcT_l + SE, Ta_c + SE, nullptr, 1.f};
    gemmN(t, 4, S_DIM, E_DIM, S_DIM);
    splitT(Ta_c, orT_h, orT_l, S_DIM, E_DIM, B_DIM);
    t = GTable{};
    t.s[0] = {dctI_h, dctI_l, orT_h,      orT_l,      outc,      nullptr, 1.f};
    t.s[1] = {dctI_h, dctI_l, orT_h + SE, orT_l + SE, outc + SE, nullptr, 1.f};
    gemmN(t, 2, S_DIM, E_DIM, S_DIM);

    /* ============ cross-domain MHA + fusion ============ */
    stack3_bf16<<<(unsigned)((3 * BSE + 255) / 256), 256>>>(P1, P2, outw, outc, xstk_h, xstk_l);
    split(mha_iw, w_h, w_l, (size_t)3 * E_DIM * E_DIM);
    gemm1(xstk_h, xstk_l, w_h, w_l, mha_ib, qkv, T3_DIM, 3 * E_DIM, E_DIM);
    mha_small_attn<<<(BS_DIM * 16 * 32) / 256, 256>>>(qkv, att);
    split(att, att_h, att_l, 3 * BSE);
    split(mha_ow, w_h, w_l, EE);
    gemm1(att_h, att_l, w_h, w_l, mha_ob, corr, T3_DIM, E_DIM, E_DIM);
    split(corr, corr_h, corr_l, 3 * BSE);
    split(fus_W, w_h, w_l, (size_t)3 * E_DIM * E_DIM);
    gemm1(corr_h, corr_l, w_h, w_l, fus_b, out, BS_DIM, E_DIM, 3 * E_DIM);
}